// round 8
// baseline (speedup 1.0000x reference)
#include <cuda_runtime.h>
#include <cuda_bf16.h>
#include <cstdint>

// ===========================================================================
// Scratch (static __device__ globals).
// Activations: bf16 hi plane + fp8 pair plane (Ah8|Al8 per 32-k group).
// Weights: bf16 hi plane + fp8 pair plane (Wl8|Wh8 per 32-k group).
// ===========================================================================
__device__ __nv_bfloat16 g_Ahi[1024 * 4096];
__device__ uint8_t       g_A8 [1024 * 4096 * 2];
__device__ __nv_bfloat16 g_Bhi[1024 * 4096];
__device__ uint8_t       g_B8 [1024 * 4096 * 2];
__device__ __nv_bfloat16 g_Whi[37748736];
__device__ uint8_t       g_W8 [75497472];

static const size_t W_OFF1 = 0;
static const size_t W_OFF2 = 8388608;
static const size_t W_OFF3 = 25165824;
static const size_t W_OFFO = 33554432;

// ===========================================================================
// PTX helpers (sm_80/sm_89-era, valid on plain compute_103)
// ===========================================================================
__device__ __forceinline__ uint32_t smem_u32(const void* p) {
    uint32_t a;
    asm("{ .reg .u64 t; cvta.to.shared.u64 t, %1; cvt.u32.u64 %0, t; }" : "=r"(a) : "l"(p));
    return a;
}
#define CP_ASYNC16(sa, ga) \
    asm volatile("cp.async.cg.shared.global [%0], [%1], 16;" ::"r"(sa), "l"(ga) : "memory")
#define CP_COMMIT() asm volatile("cp.async.commit_group;" ::: "memory")
#define CP_WAIT1() asm volatile("cp.async.wait_group 1;" ::: "memory")

#define LDMX4(r0, r1, r2, r3, addr)                                              \
    asm volatile("ldmatrix.sync.aligned.m8n8.x4.shared.b16 {%0,%1,%2,%3}, [%4];" \
                 : "=r"(r0), "=r"(r1), "=r"(r2), "=r"(r3) : "r"(addr))

#define MMA16816(c, a, b0, b1)                                                  \
    asm volatile(                                                               \
        "mma.sync.aligned.m16n8k16.row.col.f32.bf16.bf16.f32 "                  \
        "{%0,%1,%2,%3}, {%4,%5,%6,%7}, {%8,%9}, {%0,%1,%2,%3};"                 \
        : "+f"((c)[0]), "+f"((c)[1]), "+f"((c)[2]), "+f"((c)[3])                \
        : "r"((a)[0]), "r"((a)[1]), "r"((a)[2]), "r"((a)[3]), "r"(b0), "r"(b1))

#define MMA8(c, a, b0, b1)                                                      \
    asm volatile(                                                               \
        "mma.sync.aligned.m16n8k32.row.col.f32.e4m3.e4m3.f32 "                  \
        "{%0,%1,%2,%3}, {%4,%5,%6,%7}, {%8,%9}, {%0,%1,%2,%3};"                 \
        : "+f"((c)[0]), "+f"((c)[1]), "+f"((c)[2]), "+f"((c)[3])                \
        : "r"((a)[0]), "r"((a)[1]), "r"((a)[2]), "r"((a)[3]), "r"(b0), "r"(b1))

// packs: result byte1 = e4m3(a), byte0 = e4m3(b)
__device__ __forceinline__ uint16_t e4m3x2(float a, float b) {
    uint16_t d;
    asm("cvt.rn.satfinite.e4m3x2.f32 %0, %1, %2;" : "=h"(d) : "f"(a), "f"(b));
    return d;
}
__device__ __forceinline__ uint32_t pack_bf2(float a, float b) {
    __nv_bfloat162 t = __floats2bfloat162_rn(a, b);
    return *reinterpret_cast<uint32_t*>(&t);
}
__device__ __forceinline__ float clip1f(float x) { return fminf(fmaxf(x, -1.f), 1.f); }

// ---------------------------------------------------------------------------
// KAN activation (constant-folded partial Cox-de Boor; validated).
// ---------------------------------------------------------------------------
__device__ __forceinline__ float kan_eval(float x, const float* __restrict__ cps, float rwv) {
    float t = tanhf(x);
    const float kn[12] = {-1.f, -1.f, -1.f, -1.f, -0.6f, -0.2f, 0.2f, 0.6f, 1.f, 1.f, 1.f, 1.f};
    float c[8];
#pragma unroll
    for (int i = 0; i < 8; ++i) c[i] = (t >= kn[i] && t < kn[i + 1]) ? 1.f : 0.f;
#pragma unroll
    for (int dg = 1; dg <= 3; ++dg) {
#pragma unroll
        for (int i = 0; i < 7; ++i) {
            if (i < 8 - dg) {
                const float d1 = kn[i + dg] - kn[i];
                const float d2 = kn[i + dg + 1] - kn[i + 1];
                float t1 = (d1 > 1e-10f) ? ((t - kn[i]) * (1.0f / d1)) * c[i] : 0.f;
                float t2 = (d2 > 1e-10f) ? ((kn[i + dg + 1] - t) * (1.0f / d2)) * c[i + 1] : 0.f;
                c[i] = t1 + t2;
            }
        }
    }
    float s = 0.f;
#pragma unroll
    for (int j = 0; j < 8; ++j) s = fmaf(c[j], cps[j], s);
    s *= rwv;
    return fminf(fmaxf(s, -10.f), 10.f);
}

// ===========================================================================
// Weight split: fp32 -> bf16 hi + fp8 pair plane.
//   Whi[n][k] bf16;  W8[n][2K]: group c (32 k): bytes [0..31]=e4m3(Wl*2^12),
//   [32..63]=e4m3(Wh*2^4).
// kshift = log2(K).
// ===========================================================================
__global__ void wsplit(const float4* __restrict__ w, __nv_bfloat16* __restrict__ hi,
                       uint8_t* __restrict__ w8, int kshift, int n4) {
    int i = blockIdx.x * blockDim.x + threadIdx.x;
    if (i >= n4) return;
    const int K = 1 << kshift;
    const int k = (i << 2) & (K - 1);
    const int row = (i << 2) >> kshift;
    float4 v = w[i];
    __nv_bfloat16 h0 = __float2bfloat16_rn(v.x), h1 = __float2bfloat16_rn(v.y);
    __nv_bfloat16 h2 = __float2bfloat16_rn(v.z), h3 = __float2bfloat16_rn(v.w);
    float f0 = __bfloat162float(h0), f1 = __bfloat162float(h1);
    float f2 = __bfloat162float(h2), f3 = __bfloat162float(h3);
    uint32_t hi01 = ((uint32_t)__bfloat16_as_ushort(h1) << 16) | __bfloat16_as_ushort(h0);
    uint32_t hi23 = ((uint32_t)__bfloat16_as_ushort(h3) << 16) | __bfloat16_as_ushort(h2);
    *(uint2*)(hi + (size_t)row * K + k) = make_uint2(hi01, hi23);
    // fp8 planes
    const size_t b8 = (size_t)row * 2 * K + (k >> 5) * 64 + (k & 31);
    uint32_t wl = (uint32_t)e4m3x2((v.y - f1) * 4096.f, (v.x - f0) * 4096.f) |
                  ((uint32_t)e4m3x2((v.w - f3) * 4096.f, (v.z - f2) * 4096.f) << 16);
    uint32_t wh = (uint32_t)e4m3x2(f1 * 16.f, f0 * 16.f) |
                  ((uint32_t)e4m3x2(f3 * 16.f, f2 * 16.f) << 16);
    *(uint32_t*)(w8 + b8) = wl;
    *(uint32_t*)(w8 + b8 + 32) = wh;
}

// ===========================================================================
// LayerNorm: fp32 -> bf16 hi + fp8 pair plane (eA = 0: Ah8=e4m3(v), Al8=e4m3(al*256)).
// ===========================================================================
__global__ void ln_kernel(const float* __restrict__ x, __nv_bfloat16* __restrict__ yh,
                          uint8_t* __restrict__ y8) {
    const int D = 2048;
    const float* xr = x + (size_t)blockIdx.x * D;
    float s = 0.f, q = 0.f;
#pragma unroll
    for (int it = 0; it < 2; ++it) {
        float4 v = *(const float4*)(xr + threadIdx.x * 4 + it * 1024);
        s += (v.x + v.y) + (v.z + v.w);
        q += v.x * v.x + v.y * v.y + v.z * v.z + v.w * v.w;
    }
#pragma unroll
    for (int o = 16; o > 0; o >>= 1) {
        s += __shfl_xor_sync(~0u, s, o);
        q += __shfl_xor_sync(~0u, q, o);
    }
    __shared__ float ss[8], qq[8], mu_s, inv_s;
    if ((threadIdx.x & 31) == 0) { ss[threadIdx.x >> 5] = s; qq[threadIdx.x >> 5] = q; }
    __syncthreads();
    if (threadIdx.x == 0) {
        float ts = 0.f, tq = 0.f;
#pragma unroll
        for (int i = 0; i < 8; ++i) { ts += ss[i]; tq += qq[i]; }
        float mu = ts * (1.f / D);
        mu_s = mu;
        inv_s = rsqrtf(tq * (1.f / D) - mu * mu + 1e-5f);
    }
    __syncthreads();
    const float mu = mu_s, inv = inv_s;
    const size_t rb = (size_t)blockIdx.x * D;
    const size_t rb8 = (size_t)blockIdx.x * 2 * D;
#pragma unroll
    for (int it = 0; it < 2; ++it) {
        int i = threadIdx.x * 4 + it * 1024;
        float4 v = *(const float4*)(xr + i);
        float f0 = (v.x - mu) * inv, f1 = (v.y - mu) * inv;
        float f2 = (v.z - mu) * inv, f3 = (v.w - mu) * inv;
        __nv_bfloat16 h0 = __float2bfloat16_rn(f0), h1 = __float2bfloat16_rn(f1);
        __nv_bfloat16 h2 = __float2bfloat16_rn(f2), h3 = __float2bfloat16_rn(f3);
        float g0 = __bfloat162float(h0), g1 = __bfloat162float(h1);
        float g2 = __bfloat162float(h2), g3 = __bfloat162float(h3);
        uint32_t hi01 = ((uint32_t)__bfloat16_as_ushort(h1) << 16) | __bfloat16_as_ushort(h0);
        uint32_t hi23 = ((uint32_t)__bfloat16_as_ushort(h3) << 16) | __bfloat16_as_ushort(h2);
        *(uint2*)(yh + rb + i) = make_uint2(hi01, hi23);
        const size_t b8 = rb8 + (i >> 5) * 64 + (i & 31);
        uint32_t ah = (uint32_t)e4m3x2(f1, f0) | ((uint32_t)e4m3x2(f3, f2) << 16);
        uint32_t al = (uint32_t)e4m3x2((f1 - g1) * 256.f, (f0 - g0) * 256.f) |
                      ((uint32_t)e4m3x2((f3 - g3) * 256.f, (f2 - g2) * 256.f) << 16);
        *(uint32_t*)(y8 + b8) = ah;
        *(uint32_t*)(y8 + b8 + 32) = al;
    }
}

// ===========================================================================
// GEMM: main product bf16 (exact hi planes), cross terms fused into fp8
// m16n8k32 MMAs: [Ah8|Al8] . [Wl8|Wh8] over concat-K, separate fp32 acc,
// merged in epilogue: out = acc_m + acc_c * cross_scale + bias.
// BM=BN=128, BK=32, 8 warps (warp tile 64x32), 3-stage cp.async, 80B rows.
// KAN=1: spline + pair transform -> bf16 hi + fp8 pair planes (eA=4).
// KAN=0: fp32 out.
// ===========================================================================
template <int KAN>
__global__ void __launch_bounds__(256, 1)
gemm_mma(const __nv_bfloat16* __restrict__ Ah, const uint8_t* __restrict__ A8,
         const __nv_bfloat16* __restrict__ Wh, const uint8_t* __restrict__ W8,
         const float* __restrict__ bias, const float* __restrict__ cp,
         const float* __restrict__ rw, float* __restrict__ Cf,
         __nv_bfloat16* __restrict__ Chi, uint8_t* __restrict__ C8,
         int N, int K, float cross_scale) {
    extern __shared__ char smem[];
    float* smf = (float*)smem;
    const uint32_t sb = smem_u32(smem);
    constexpr uint32_t PARAMB = 5120, PLANE = 10240, BOFF = 20480, STAGE = 40960;

    const int tid = threadIdx.x, lane = tid & 31, wid = tid >> 5;
    const int warp_m = wid & 1, warp_n = wid >> 1;
    const int row0 = blockIdx.y * 128, col0 = blockIdx.x * 128;

    for (int i = tid; i < 128; i += 256) {
        smf[i] = bias[col0 + i];
        if (KAN) smf[128 + i] = rw[col0 + i];
    }
    if (KAN)
        for (int i = tid; i < 1024; i += 256)
            smf[256 + i] = cp[(size_t)(col0 + (i >> 3)) * 9 + (i & 7)];

    // loader: 2048 x 16B per stage; planes: A-hi, A-8, W-hi, W-8 (each 128x64B @80B pitch)
    auto issue = [&](int kt, int st) {
#pragma unroll
        for (int i = 0; i < 8; ++i) {
            int id = tid + 256 * i;
            int half = id >> 10;          // 0 = A, 1 = W
            int rem = id & 1023;
            int plane = rem >> 9;         // 0 = bf16 hi, 1 = fp8 pair
            int r = (rem >> 2) & 127;
            int c16 = rem & 3;
            const char* gp;
            if (half == 0)
                gp = plane ? (const char*)(A8 + (size_t)(row0 + r) * 2 * K + kt * 64 + c16 * 16)
                           : (const char*)(Ah + (size_t)(row0 + r) * K + kt * 32 + c16 * 8);
            else
                gp = plane ? (const char*)(W8 + (size_t)(col0 + r) * 2 * K + kt * 64 + c16 * 16)
                           : (const char*)(Wh + (size_t)(col0 + r) * K + kt * 32 + c16 * 8);
            uint32_t sa = sb + PARAMB + st * STAGE + half * BOFF + plane * PLANE +
                          r * 80 + c16 * 16;
            CP_ASYNC16(sa, gp);
        }
    };

    const int NC = K >> 5;
    issue(0, 0); CP_COMMIT();
    issue(1, 1); CP_COMMIT();

    float am[4][4][4], ac[4][4][4];
#pragma unroll
    for (int a = 0; a < 4; ++a)
#pragma unroll
        for (int b = 0; b < 4; ++b)
#pragma unroll
            for (int d = 0; d < 4; ++d) { am[a][b][d] = 0.f; ac[a][b][d] = 0.f; }

    uint32_t a_row[4], b_row[2];
#pragma unroll
    for (int mf = 0; mf < 4; ++mf)
        a_row[mf] = (uint32_t)(warp_m * 64 + mf * 16 + (lane & 15)) * 80;
#pragma unroll
    for (int nf2 = 0; nf2 < 2; ++nf2)
        b_row[nf2] =
            (uint32_t)(warp_n * 32 + nf2 * 16 + (lane & 7) + ((lane >> 4) & 1) * 8) * 80;
    const uint32_t a_koff = (uint32_t)(lane >> 4) * 16;       // bf16 A
    const uint32_t b_koff = (uint32_t)((lane >> 3) & 1) * 16; // bf16 W
    // fp8 A: row = (lane&7)+((lane>>3)&1)*8 -> same as (lane&15); koff = ((lane>>4)&1)*16
    uint32_t a8_row[4];
#pragma unroll
    for (int mf = 0; mf < 4; ++mf)
        a8_row[mf] = (uint32_t)(warp_m * 64 + mf * 16 + (lane & 7) + ((lane >> 3) & 1) * 8) * 80;
    const uint32_t a8_koff = (uint32_t)((lane >> 4) & 1) * 16;
    // fp8 W: col = (lane&7)+((lane>>4)&1)*8 ; koff = ((lane>>3)&1)*16  (== b_row/b_koff)

    for (int kt = 0; kt < NC; ++kt) {
        CP_WAIT1();
        __syncthreads();
        const int nx = kt + 2;
        if (nx < NC) issue(nx, nx % 3);
        CP_COMMIT();

        const uint32_t base = sb + PARAMB + (uint32_t)(kt % 3) * STAGE;
        // ---- bf16 main: 2 x k16 ----
#pragma unroll
        for (int k16 = 0; k16 < 2; ++k16) {
            const uint32_t kb = (uint32_t)k16 * 32;
            uint32_t ah[4][4], bh[4][2];
#pragma unroll
            for (int nf2 = 0; nf2 < 2; ++nf2) {
                uint32_t r0, r1, r2, r3;
                LDMX4(r0, r1, r2, r3, base + BOFF + b_row[nf2] + kb + b_koff);
                bh[nf2 * 2][0] = r0; bh[nf2 * 2][1] = r1;
                bh[nf2 * 2 + 1][0] = r2; bh[nf2 * 2 + 1][1] = r3;
            }
#pragma unroll
            for (int mf = 0; mf < 4; ++mf)
                LDMX4(ah[mf][0], ah[mf][1], ah[mf][2], ah[mf][3],
                      base + a_row[mf] + kb + a_koff);
#pragma unroll
            for (int mf = 0; mf < 4; ++mf)
#pragma unroll
                for (int nf = 0; nf < 4; ++nf)
                    MMA16816(am[mf][nf], ah[mf], bh[nf][0], bh[nf][1]);
        }
        // ---- fp8 cross: 2 x k32 (Ah8.Wl8 then Al8.Wh8) ----
#pragma unroll
        for (int sel = 0; sel < 2; ++sel) {
            const uint32_t so = (uint32_t)sel * 32;
            uint32_t a8[4][4], b8[4][2];
#pragma unroll
            for (int nf2 = 0; nf2 < 2; ++nf2) {
                uint32_t r0, r1, r2, r3;
                LDMX4(r0, r1, r2, r3, base + BOFF + PLANE + b_row[nf2] + b_koff + so);
                b8[nf2 * 2][0] = r0; b8[nf2 * 2][1] = r1;
                b8[nf2 * 2 + 1][0] = r2; b8[nf2 * 2 + 1][1] = r3;
            }
#pragma unroll
            for (int mf = 0; mf < 4; ++mf)
                LDMX4(a8[mf][0], a8[mf][1], a8[mf][2], a8[mf][3],
                      base + PLANE + a8_row[mf] + a8_koff + so);
#pragma unroll
            for (int mf = 0; mf < 4; ++mf)
#pragma unroll
                for (int nf = 0; nf < 4; ++nf)
                    MMA8(ac[mf][nf], a8[mf], b8[nf][0], b8[nf][1]);
        }
    }

    // ---- epilogue: generator g = lane & 3; g in {2,3} -> identity ----
    const int g = lane & 3;
    const float cA = (g < 2) ? 0.05f : 0.f;
    const float sgn = (g == 1) ? -1.f : 1.f;
    const float cs = cross_scale;

#pragma unroll
    for (int nf = 0; nf < 4; ++nf) {
        const int cl = warp_n * 32 + nf * 8 + 2 * (lane & 3);
        const float b0 = smf[cl], b1 = smf[cl + 1];
        float rw0 = 0.f, rw1 = 0.f, cps0[8], cps1[8];
        if (KAN) {
            rw0 = smf[128 + cl];
            rw1 = smf[128 + cl + 1];
#pragma unroll
            for (int j = 0; j < 8; ++j) {
                cps0[j] = smf[256 + cl * 8 + j];
                cps1[j] = smf[256 + (cl + 1) * 8 + j];
            }
        }
#pragma unroll
        for (int mf = 0; mf < 4; ++mf) {
            const int m0 = row0 + warp_m * 64 + mf * 16 + (lane >> 2);
            float v0 = fmaf(ac[mf][nf][0], cs, am[mf][nf][0]) + b0;
            float v1 = fmaf(ac[mf][nf][1], cs, am[mf][nf][1]) + b1;
            float v2 = fmaf(ac[mf][nf][2], cs, am[mf][nf][2]) + b0;
            float v3 = fmaf(ac[mf][nf][3], cs, am[mf][nf][3]) + b1;
            if (KAN) {
                v0 = kan_eval(v0, cps0, rw0);
                v1 = kan_eval(v1, cps1, rw1);
                v2 = kan_eval(v2, cps0, rw0);
                v3 = kan_eval(v3, cps1, rw1);
                float t = v0;
                v0 = fmaf(cA, clip1f(sgn * v1), v0);
                v1 = fmaf(cA, clip1f(t), v1);
                t = v2;
                v2 = fmaf(cA, clip1f(sgn * v3), v2);
                v3 = fmaf(cA, clip1f(t), v3);
                __nv_bfloat16 h0 = __float2bfloat16_rn(v0), h1 = __float2bfloat16_rn(v1);
                __nv_bfloat16 h2 = __float2bfloat16_rn(v2), h3 = __float2bfloat16_rn(v3);
                const size_t i0 = (size_t)m0 * N + col0 + cl;
                const size_t i1 = (size_t)(m0 + 8) * N + col0 + cl;
                *(uint32_t*)(Chi + i0) =
                    ((uint32_t)__bfloat16_as_ushort(h1) << 16) | __bfloat16_as_ushort(h0);
                *(uint32_t*)(Chi + i1) =
                    ((uint32_t)__bfloat16_as_ushort(h3) << 16) | __bfloat16_as_ushort(h2);
                // fp8 pair plane, eA = 4: Ah8 = e4m3(v*16), Al8 = e4m3((v-hi)*4096)
                const int grp = (col0 + cl) >> 5, off = cl & 31;
                const size_t b80 = (size_t)m0 * 2 * N + grp * 64 + off;
                const size_t b81 = (size_t)(m0 + 8) * 2 * N + grp * 64 + off;
                *(uint16_t*)(C8 + b80) = e4m3x2(v1 * 16.f, v0 * 16.f);
                *(uint16_t*)(C8 + b81) = e4m3x2(v3 * 16.f, v2 * 16.f);
                *(uint16_t*)(C8 + b80 + 32) =
                    e4m3x2((v1 - __bfloat162float(h1)) * 4096.f,
                           (v0 - __bfloat162float(h0)) * 4096.f);
                *(uint16_t*)(C8 + b81 + 32) =
                    e4m3x2((v3 - __bfloat162float(h3)) * 4096.f,
                           (v2 - __bfloat162float(h2)) * 4096.f);
            } else {
                const size_t i0 = (size_t)m0 * N + col0 + cl;
                const size_t i1 = (size_t)(m0 + 8) * N + col0 + cl;
                *(float2*)(Cf + i0) = make_float2(v0, v1);
                *(float2*)(Cf + i1) = make_float2(v2, v3);
            }
        }
    }
}

// ===========================================================================
// Launch
// ===========================================================================
static constexpr int SMEM_BYTES = 5120 + 3 * 40960;  // 128000

extern "C" void kernel_launch(void* const* d_in, const int* in_sizes, int n_in,
                              void* d_out, int out_size) {
    const float* x = (const float*)d_in[0];
    const float* W1 = (const float*)d_in[1];
    const float* b1 = (const float*)d_in[2];
    const float* cp1 = (const float*)d_in[3];
    const float* rw1 = (const float*)d_in[4];
    const float* W2 = (const float*)d_in[5];
    const float* b2 = (const float*)d_in[6];
    const float* cp2 = (const float*)d_in[7];
    const float* rw2 = (const float*)d_in[8];
    const float* W3 = (const float*)d_in[9];
    const float* b3 = (const float*)d_in[10];
    const float* cp3 = (const float*)d_in[11];
    const float* rw3 = (const float*)d_in[12];
    const float* Wo = (const float*)d_in[13];
    const float* bo = (const float*)d_in[14];

    static __nv_bfloat16 *Ah = nullptr, *Bh, *Wh;
    static uint8_t *A8, *B8, *W8;
    if (!Ah) {
        cudaGetSymbolAddress((void**)&Ah, g_Ahi);
        cudaGetSymbolAddress((void**)&A8, g_A8);
        cudaGetSymbolAddress((void**)&Bh, g_Bhi);
        cudaGetSymbolAddress((void**)&B8, g_B8);
        cudaGetSymbolAddress((void**)&Wh, g_Whi);
        cudaGetSymbolAddress((void**)&W8, g_W8);
        cudaFuncSetAttribute(gemm_mma<1>, cudaFuncAttributeMaxDynamicSharedMemorySize, SMEM_BYTES);
        cudaFuncSetAttribute(gemm_mma<0>, cudaFuncAttributeMaxDynamicSharedMemorySize, SMEM_BYTES);
    }

    const float CS_LN = 1.f / 4096.f;     // eA=0: 2^-12
    const float CS_KAN = 1.f / 65536.f;   // eA=4: 2^-16

    // ---- weight split prepass ----
    wsplit<<<8388608 / 4 / 256, 256>>>((const float4*)W1, Wh + W_OFF1, W8 + 2 * W_OFF1,
                                       11, 8388608 / 4);
    wsplit<<<16777216 / 4 / 256, 256>>>((const float4*)W2, Wh + W_OFF2, W8 + 2 * W_OFF2,
                                        12, 16777216 / 4);
    wsplit<<<8388608 / 4 / 256, 256>>>((const float4*)W3, Wh + W_OFF3, W8 + 2 * W_OFF3,
                                       12, 8388608 / 4);
    wsplit<<<4194304 / 4 / 256, 256>>>((const float4*)Wo, Wh + W_OFFO, W8 + 2 * W_OFFO,
                                       11, 4194304 / 4);

    // ---- LN ----
    ln_kernel<<<1024, 256>>>(x, Ah, A8);

    // ---- GEMM chain ----
    gemm_mma<1><<<dim3(32, 8), 256, SMEM_BYTES>>>(Ah, A8, Wh + W_OFF1, W8 + 2 * W_OFF1,
                                                  b1, cp1, rw1, nullptr, Bh, B8,
                                                  4096, 2048, CS_LN);
    gemm_mma<1><<<dim3(32, 8), 256, SMEM_BYTES>>>(Bh, B8, Wh + W_OFF2, W8 + 2 * W_OFF2,
                                                  b2, cp2, rw2, nullptr, Ah, A8,
                                                  4096, 4096, CS_KAN);
    gemm_mma<1><<<dim3(16, 8), 256, SMEM_BYTES>>>(Ah, A8, Wh + W_OFF3, W8 + 2 * W_OFF3,
                                                  b3, cp3, rw3, nullptr, Bh, B8,
                                                  2048, 4096, CS_KAN);
    gemm_mma<0><<<dim3(16, 8), 256, SMEM_BYTES>>>(Bh, B8, Wh + W_OFFO, W8 + 2 * W_OFFO,
                                                  bo, nullptr, nullptr, (float*)d_out,
                                                  nullptr, nullptr, 2048, 2048, CS_KAN);
}

// round 9
// speedup vs baseline: 1.4815x; 1.4815x over previous
#include <cuda_runtime.h>
#include <cuda_fp16.h>
#include <cstdint>

// ===========================================================================
// Scratch (static __device__ globals — no runtime allocation).
// Activations: dual fp16 planes (hi + residual lo) -> ~22-bit precision.
// Weights: single fp16 plane (11-bit) -> sole quantization error source.
// ===========================================================================
__device__ __half g_Ahi[1024 * 4096];
__device__ __half g_Alo[1024 * 4096];
__device__ __half g_Bhi[1024 * 4096];
__device__ __half g_Blo[1024 * 4096];
__device__ __half g_Wh [37748736];

static const size_t W_OFF1 = 0;
static const size_t W_OFF2 = 8388608;
static const size_t W_OFF3 = 25165824;
static const size_t W_OFFO = 33554432;

// ===========================================================================
// PTX helpers (sm_80-era, valid on plain compute_103)
// ===========================================================================
__device__ __forceinline__ uint32_t smem_u32(const void* p) {
    uint32_t a;
    asm("{ .reg .u64 t; cvta.to.shared.u64 t, %1; cvt.u32.u64 %0, t; }" : "=r"(a) : "l"(p));
    return a;
}
#define CP_ASYNC16(sa, ga) \
    asm volatile("cp.async.cg.shared.global [%0], [%1], 16;" ::"r"(sa), "l"(ga) : "memory")
#define CP_COMMIT() asm volatile("cp.async.commit_group;" ::: "memory")
#define CP_WAIT1() asm volatile("cp.async.wait_group 1;" ::: "memory")

#define LDMX4(r0, r1, r2, r3, addr)                                              \
    asm volatile("ldmatrix.sync.aligned.m8n8.x4.shared.b16 {%0,%1,%2,%3}, [%4];" \
                 : "=r"(r0), "=r"(r1), "=r"(r2), "=r"(r3) : "r"(addr))

#define MMAF16(c, a, b0, b1)                                                    \
    asm volatile(                                                               \
        "mma.sync.aligned.m16n8k16.row.col.f32.f16.f16.f32 "                    \
        "{%0,%1,%2,%3}, {%4,%5,%6,%7}, {%8,%9}, {%0,%1,%2,%3};"                 \
        : "+f"((c)[0]), "+f"((c)[1]), "+f"((c)[2]), "+f"((c)[3])                \
        : "r"((a)[0]), "r"((a)[1]), "r"((a)[2]), "r"((a)[3]), "r"(b0), "r"(b1))

__device__ __forceinline__ uint32_t pack_h2(float a, float b) {
    __half2 t = __floats2half2_rn(a, b);
    return *reinterpret_cast<uint32_t*>(&t);
}
__device__ __forceinline__ float clip1f(float x) { return fminf(fmaxf(x, -1.f), 1.f); }

// ---------------------------------------------------------------------------
// KAN activation (constant-folded partial Cox-de Boor; validated R4/R6).
// ---------------------------------------------------------------------------
__device__ __forceinline__ float kan_eval(float x, const float* __restrict__ cps, float rwv) {
    float t = tanhf(x);
    const float kn[12] = {-1.f, -1.f, -1.f, -1.f, -0.6f, -0.2f, 0.2f, 0.6f, 1.f, 1.f, 1.f, 1.f};
    float c[8];
#pragma unroll
    for (int i = 0; i < 8; ++i) c[i] = (t >= kn[i] && t < kn[i + 1]) ? 1.f : 0.f;
#pragma unroll
    for (int dg = 1; dg <= 3; ++dg) {
#pragma unroll
        for (int i = 0; i < 7; ++i) {
            if (i < 8 - dg) {
                const float d1 = kn[i + dg] - kn[i];
                const float d2 = kn[i + dg + 1] - kn[i + 1];
                float t1 = (d1 > 1e-10f) ? ((t - kn[i]) * (1.0f / d1)) * c[i] : 0.f;
                float t2 = (d2 > 1e-10f) ? ((kn[i + dg + 1] - t) * (1.0f / d2)) * c[i + 1] : 0.f;
                c[i] = t1 + t2;
            }
        }
    }
    float s = 0.f;
#pragma unroll
    for (int j = 0; j < 8; ++j) s = fmaf(c[j], cps[j], s);
    s *= rwv;
    return fminf(fmaxf(s, -10.f), 10.f);
}

// ===========================================================================
// Weight convert: fp32 -> single fp16 plane.
// ===========================================================================
__global__ void wsplit(const float4* __restrict__ w, uint2* __restrict__ h, int n4) {
    int i = blockIdx.x * blockDim.x + threadIdx.x;
    if (i >= n4) return;
    float4 v = w[i];
    h[i] = make_uint2(pack_h2(v.x, v.y), pack_h2(v.z, v.w));
}

// ===========================================================================
// LayerNorm: fp32 -> fp16 hi + fp16 residual planes. 1 row/block, D=2048.
// ===========================================================================
__global__ void ln_kernel(const float* __restrict__ x, __half* __restrict__ yh,
                          __half* __restrict__ yl) {
    const int D = 2048;
    const float* xr = x + (size_t)blockIdx.x * D;
    float s = 0.f, q = 0.f;
#pragma unroll
    for (int it = 0; it < 2; ++it) {
        float4 v = *(const float4*)(xr + threadIdx.x * 4 + it * 1024);
        s += (v.x + v.y) + (v.z + v.w);
        q += v.x * v.x + v.y * v.y + v.z * v.z + v.w * v.w;
    }
#pragma unroll
    for (int o = 16; o > 0; o >>= 1) {
        s += __shfl_xor_sync(~0u, s, o);
        q += __shfl_xor_sync(~0u, q, o);
    }
    __shared__ float ss[8], qq[8], mu_s, inv_s;
    if ((threadIdx.x & 31) == 0) { ss[threadIdx.x >> 5] = s; qq[threadIdx.x >> 5] = q; }
    __syncthreads();
    if (threadIdx.x == 0) {
        float ts = 0.f, tq = 0.f;
#pragma unroll
        for (int i = 0; i < 8; ++i) { ts += ss[i]; tq += qq[i]; }
        float mu = ts * (1.f / D);
        mu_s = mu;
        inv_s = rsqrtf(tq * (1.f / D) - mu * mu + 1e-5f);
    }
    __syncthreads();
    const float mu = mu_s, inv = inv_s;
    const size_t rb = (size_t)blockIdx.x * D;
#pragma unroll
    for (int it = 0; it < 2; ++it) {
        int i = threadIdx.x * 4 + it * 1024;
        float4 v = *(const float4*)(xr + i);
        float f0 = (v.x - mu) * inv, f1 = (v.y - mu) * inv;
        float f2 = (v.z - mu) * inv, f3 = (v.w - mu) * inv;
        __half h0 = __float2half_rn(f0), h1 = __float2half_rn(f1);
        __half h2 = __float2half_rn(f2), h3 = __float2half_rn(f3);
        uint32_t p01, p23;
        { __half2 t = __halves2half2(h0, h1); p01 = *(uint32_t*)&t; }
        { __half2 t = __halves2half2(h2, h3); p23 = *(uint32_t*)&t; }
        *(uint2*)(yh + rb + i) = make_uint2(p01, p23);
        *(uint2*)(yl + rb + i) =
            make_uint2(pack_h2(f0 - __half2float(h0), f1 - __half2float(h1)),
                       pack_h2(f2 - __half2float(h2), f3 - __half2float(h3)));
    }
}

// ===========================================================================
// GEMM via mma.sync m16n8k16 fp16, x2-product, shared fp32 accumulator:
//   acc += Ah.Wh + Al.Wh   (== (Ah+Al).Wh; dropped A.Wl ~ 2^-11)
// BM=BN=128, BK=32, 8 warps (warp tile 64x32), 3-stage cp.async,
// 80B-pitch rows -> conflict-free ldmatrix. Cross MMAs reuse B fragments.
// KAN=1: bias + spline + pair transform -> fp16 hi + lo planes.
// KAN=0: bias -> fp32 out.
// SMEM: [0,5120) params; stage st at 5120+st*30720: {A-hi, A-lo, W-hi}
//       each 128 rows x 80 B.
// ===========================================================================
template <int KAN>
__global__ void __launch_bounds__(256, 1)
gemm_mma(const __half* __restrict__ Ah, const __half* __restrict__ Al,
         const __half* __restrict__ Wh,
         const float* __restrict__ bias, const float* __restrict__ cp,
         const float* __restrict__ rw, float* __restrict__ Cf,
         __half* __restrict__ Chi, __half* __restrict__ Clo,
         int N, int K) {
    extern __shared__ char smem[];
    float* smf = (float*)smem;
    const uint32_t sb = smem_u32(smem);
    constexpr uint32_t PARAMB = 5120, PLANE = 10240, STAGE = 30720;

    const int tid = threadIdx.x, lane = tid & 31, wid = tid >> 5;
    const int warp_m = wid & 1, warp_n = wid >> 1;
    const int row0 = blockIdx.y * 128, col0 = blockIdx.x * 128;

    for (int i = tid; i < 128; i += 256) {
        smf[i] = bias[col0 + i];
        if (KAN) smf[128 + i] = rw[col0 + i];
    }
    if (KAN)
        for (int i = tid; i < 1024; i += 256)
            smf[256 + i] = cp[(size_t)(col0 + (i >> 3)) * 9 + (i & 7)];

    // loader: 1536 x 16B per stage (3 planes x 128 rows x 4 chunks), 6/thread
    auto issue = [&](int kt, int st) {
#pragma unroll
        for (int i = 0; i < 6; ++i) {
            int id = tid + 256 * i;
            int plane = id >> 9;          // 0 = A-hi, 1 = A-lo, 2 = W-hi
            int rem = id & 511;
            int r = rem >> 2, c16 = rem & 3;
            const __half* gp =
                (plane == 0) ? Ah + (size_t)(row0 + r) * K + kt * 32 + c16 * 8
                : (plane == 1) ? Al + (size_t)(row0 + r) * K + kt * 32 + c16 * 8
                               : Wh + (size_t)(col0 + r) * K + kt * 32 + c16 * 8;
            uint32_t sa = sb + PARAMB + st * STAGE + plane * PLANE + r * 80 + c16 * 16;
            CP_ASYNC16(sa, gp);
        }
    };

    const int NC = K >> 5;
    issue(0, 0); CP_COMMIT();
    issue(1, 1); CP_COMMIT();

    float acc[4][4][4];
#pragma unroll
    for (int a = 0; a < 4; ++a)
#pragma unroll
        for (int b = 0; b < 4; ++b)
#pragma unroll
            for (int d = 0; d < 4; ++d) acc[a][b][d] = 0.f;

    uint32_t a_row[4], b_row[2];
#pragma unroll
    for (int mf = 0; mf < 4; ++mf)
        a_row[mf] = (uint32_t)(warp_m * 64 + mf * 16 + (lane & 15)) * 80;
#pragma unroll
    for (int nf2 = 0; nf2 < 2; ++nf2)
        b_row[nf2] =
            (uint32_t)(warp_n * 32 + nf2 * 16 + (lane & 7) + ((lane >> 4) & 1) * 8) * 80;
    const uint32_t a_koff = (uint32_t)(lane >> 4) * 16;
    const uint32_t b_koff = (uint32_t)((lane >> 3) & 1) * 16;

    for (int kt = 0; kt < NC; ++kt) {
        CP_WAIT1();
        __syncthreads();
        const int nx = kt + 2;
        if (nx < NC) issue(nx, nx % 3);
        CP_COMMIT();

        const uint32_t base = sb + PARAMB + (uint32_t)(kt % 3) * STAGE;
#pragma unroll
        for (int k16 = 0; k16 < 2; ++k16) {
            const uint32_t kb = (uint32_t)k16 * 32;
            uint32_t ah[4][4], al[4][4], bh[4][2];
#pragma unroll
            for (int nf2 = 0; nf2 < 2; ++nf2) {
                uint32_t r0, r1, r2, r3;
                LDMX4(r0, r1, r2, r3, base + 2 * PLANE + b_row[nf2] + kb + b_koff);
                bh[nf2 * 2][0] = r0; bh[nf2 * 2][1] = r1;
                bh[nf2 * 2 + 1][0] = r2; bh[nf2 * 2 + 1][1] = r3;
            }
#pragma unroll
            for (int mf = 0; mf < 4; ++mf)
                LDMX4(ah[mf][0], ah[mf][1], ah[mf][2], ah[mf][3],
                      base + a_row[mf] + kb + a_koff);
#pragma unroll
            for (int mf = 0; mf < 4; ++mf)
#pragma unroll
                for (int nf = 0; nf < 4; ++nf)
                    MMAF16(acc[mf][nf], ah[mf], bh[nf][0], bh[nf][1]);
#pragma unroll
            for (int mf = 0; mf < 4; ++mf)
                LDMX4(al[mf][0], al[mf][1], al[mf][2], al[mf][3],
                      base + PLANE + a_row[mf] + kb + a_koff);
#pragma unroll
            for (int mf = 0; mf < 4; ++mf)
#pragma unroll
                for (int nf = 0; nf < 4; ++nf)
                    MMAF16(acc[mf][nf], al[mf], bh[nf][0], bh[nf][1]);
        }
    }

    // ---- epilogue: generator g = lane & 3; g in {2,3} -> identity ----
    const int g = lane & 3;
    const float cA = (g < 2) ? 0.05f : 0.f;
    const float sgn = (g == 1) ? -1.f : 1.f;

#pragma unroll
    for (int nf = 0; nf < 4; ++nf) {
        const int cl = warp_n * 32 + nf * 8 + 2 * (lane & 3);
        const float b0 = smf[cl], b1 = smf[cl + 1];
        float rw0 = 0.f, rw1 = 0.f, cps0[8], cps1[8];
        if (KAN) {
            rw0 = smf[128 + cl];
            rw1 = smf[128 + cl + 1];
#pragma unroll
            for (int j = 0; j < 8; ++j) {
                cps0[j] = smf[256 + cl * 8 + j];
                cps1[j] = smf[256 + (cl + 1) * 8 + j];
            }
        }
#pragma unroll
        for (int mf = 0; mf < 4; ++mf) {
            const int m0 = row0 + warp_m * 64 + mf * 16 + (lane >> 2);
            float v0 = acc[mf][nf][0] + b0, v1 = acc[mf][nf][1] + b1;
            float v2 = acc[mf][nf][2] + b0, v3 = acc[mf][nf][3] + b1;
            if (KAN) {
                v0 = kan_eval(v0, cps0, rw0);
                v1 = kan_eval(v1, cps1, rw1);
                v2 = kan_eval(v2, cps0, rw0);
                v3 = kan_eval(v3, cps1, rw1);
                float t = v0;
                v0 = fmaf(cA, clip1f(sgn * v1), v0);
                v1 = fmaf(cA, clip1f(t), v1);
                t = v2;
                v2 = fmaf(cA, clip1f(sgn * v3), v2);
                v3 = fmaf(cA, clip1f(t), v3);
                __half h0 = __float2half_rn(v0), h1 = __float2half_rn(v1);
                __half h2 = __float2half_rn(v2), h3 = __float2half_rn(v3);
                const size_t i0 = (size_t)m0 * N + col0 + cl;
                const size_t i1 = (size_t)(m0 + 8) * N + col0 + cl;
                { __half2 t2 = __halves2half2(h0, h1); *(uint32_t*)(Chi + i0) = *(uint32_t*)&t2; }
                { __half2 t2 = __halves2half2(h2, h3); *(uint32_t*)(Chi + i1) = *(uint32_t*)&t2; }
                *(uint32_t*)(Clo + i0) =
                    pack_h2(v0 - __half2float(h0), v1 - __half2float(h1));
                *(uint32_t*)(Clo + i1) =
                    pack_h2(v2 - __half2float(h2), v3 - __half2float(h3));
            } else {
                const size_t i0 = (size_t)m0 * N + col0 + cl;
                const size_t i1 = (size_t)(m0 + 8) * N + col0 + cl;
                *(float2*)(Cf + i0) = make_float2(v0, v1);
                *(float2*)(Cf + i1) = make_float2(v2, v3);
            }
        }
    }
}

// ===========================================================================
// Launch
// ===========================================================================
static constexpr int SMEM_BYTES = 5120 + 3 * 30720;  // 97280

extern "C" void kernel_launch(void* const* d_in, const int* in_sizes, int n_in,
                              void* d_out, int out_size) {
    const float* x = (const float*)d_in[0];
    const float* W1 = (const float*)d_in[1];
    const float* b1 = (const float*)d_in[2];
    const float* cp1 = (const float*)d_in[3];
    const float* rw1 = (const float*)d_in[4];
    const float* W2 = (const float*)d_in[5];
    const float* b2 = (const float*)d_in[6];
    const float* cp2 = (const float*)d_in[7];
    const float* rw2 = (const float*)d_in[8];
    const float* W3 = (const float*)d_in[9];
    const float* b3 = (const float*)d_in[10];
    const float* cp3 = (const float*)d_in[11];
    const float* rw3 = (const float*)d_in[12];
    const float* Wo = (const float*)d_in[13];
    const float* bo = (const float*)d_in[14];

    static __half *Ah = nullptr, *Al, *Bh, *Bl, *Wh;
    if (!Ah) {
        cudaGetSymbolAddress((void**)&Ah, g_Ahi);
        cudaGetSymbolAddress((void**)&Al, g_Alo);
        cudaGetSymbolAddress((void**)&Bh, g_Bhi);
        cudaGetSymbolAddress((void**)&Bl, g_Blo);
        cudaGetSymbolAddress((void**)&Wh, g_Wh);
        cudaFuncSetAttribute(gemm_mma<1>, cudaFuncAttributeMaxDynamicSharedMemorySize, SMEM_BYTES);
        cudaFuncSetAttribute(gemm_mma<0>, cudaFuncAttributeMaxDynamicSharedMemorySize, SMEM_BYTES);
    }

    // ---- weight convert prepass (fp32 -> single fp16 plane) ----
    wsplit<<<8388608 / 4 / 256, 256>>>((const float4*)W1, (uint2*)(Wh + W_OFF1), 8388608 / 4);
    wsplit<<<16777216 / 4 / 256, 256>>>((const float4*)W2, (uint2*)(Wh + W_OFF2), 16777216 / 4);
    wsplit<<<8388608 / 4 / 256, 256>>>((const float4*)W3, (uint2*)(Wh + W_OFF3), 8388608 / 4);
    wsplit<<<4194304 / 4 / 256, 256>>>((const float4*)Wo, (uint2*)(Wh + W_OFFO), 4194304 / 4);

    // ---- LN: x -> (Ah, Al) fp16 planes, K = 2048 ----
    ln_kernel<<<1024, 256>>>(x, Ah, Al);

    // ---- GEMM chain ----
    gemm_mma<1><<<dim3(32, 8), 256, SMEM_BYTES>>>(Ah, Al, Wh + W_OFF1, b1, cp1, rw1,
                                                  nullptr, Bh, Bl, 4096, 2048);
    gemm_mma<1><<<dim3(32, 8), 256, SMEM_BYTES>>>(Bh, Bl, Wh + W_OFF2, b2, cp2, rw2,
                                                  nullptr, Ah, Al, 4096, 4096);
    gemm_mma<1><<<dim3(16, 8), 256, SMEM_BYTES>>>(Ah, Al, Wh + W_OFF3, b3, cp3, rw3,
                                                  nullptr, Bh, Bl, 2048, 4096);
    gemm_mma<0><<<dim3(16, 8), 256, SMEM_BYTES>>>(Bh, Bl, Wh + W_OFFO, bo, nullptr,
                                                  nullptr, (float*)d_out, nullptr,
                                                  nullptr, 2048, 2048);
}

// round 10
// speedup vs baseline: 2.2685x; 1.5312x over previous
#include <cuda_runtime.h>
#include <cuda_fp16.h>
#include <cstdint>

// ===========================================================================
// Scratch (static __device__ globals — no runtime allocation).
// Activations: single fp16 plane ping-pong. Weights: single fp16 plane.
// ===========================================================================
__device__ __half g_A[1024 * 4096];
__device__ __half g_B[1024 * 4096];
__device__ __half g_Wh[37748736];

static const size_t W_OFF1 = 0;
static const size_t W_OFF2 = 8388608;
static const size_t W_OFF3 = 25165824;
static const size_t W_OFFO = 33554432;

// ===========================================================================
// PTX helpers (sm_80-era, valid on plain compute_103)
// ===========================================================================
__device__ __forceinline__ uint32_t smem_u32(const void* p) {
    uint32_t a;
    asm("{ .reg .u64 t; cvta.to.shared.u64 t, %1; cvt.u32.u64 %0, t; }" : "=r"(a) : "l"(p));
    return a;
}
#define CP_ASYNC16(sa, ga) \
    asm volatile("cp.async.cg.shared.global [%0], [%1], 16;" ::"r"(sa), "l"(ga) : "memory")
#define CP_COMMIT() asm volatile("cp.async.commit_group;" ::: "memory")
#define CP_WAIT1() asm volatile("cp.async.wait_group 1;" ::: "memory")

#define LDMX4(r0, r1, r2, r3, addr)                                              \
    asm volatile("ldmatrix.sync.aligned.m8n8.x4.shared.b16 {%0,%1,%2,%3}, [%4];" \
                 : "=r"(r0), "=r"(r1), "=r"(r2), "=r"(r3) : "r"(addr))

#define MMAF16(c, a, b0, b1)                                                    \
    asm volatile(                                                               \
        "mma.sync.aligned.m16n8k16.row.col.f32.f16.f16.f32 "                    \
        "{%0,%1,%2,%3}, {%4,%5,%6,%7}, {%8,%9}, {%0,%1,%2,%3};"                 \
        : "+f"((c)[0]), "+f"((c)[1]), "+f"((c)[2]), "+f"((c)[3])                \
        : "r"((a)[0]), "r"((a)[1]), "r"((a)[2]), "r"((a)[3]), "r"(b0), "r"(b1))

__device__ __forceinline__ uint32_t pack_h2(float a, float b) {
    __half2 t = __floats2half2_rn(a, b);
    return *reinterpret_cast<uint32_t*>(&t);
}
__device__ __forceinline__ float clip1f(float x) { return fminf(fmaxf(x, -1.f), 1.f); }

// ---------------------------------------------------------------------------
// KAN activation (constant-folded partial Cox-de Boor; validated R4/R6/R9).
// ---------------------------------------------------------------------------
__device__ __forceinline__ float kan_eval(float x, const float* __restrict__ cps, float rwv) {
    float t = tanhf(x);
    const float kn[12] = {-1.f, -1.f, -1.f, -1.f, -0.6f, -0.2f, 0.2f, 0.6f, 1.f, 1.f, 1.f, 1.f};
    float c[8];
#pragma unroll
    for (int i = 0; i < 8; ++i) c[i] = (t >= kn[i] && t < kn[i + 1]) ? 1.f : 0.f;
#pragma unroll
    for (int dg = 1; dg <= 3; ++dg) {
#pragma unroll
        for (int i = 0; i < 7; ++i) {
            if (i < 8 - dg) {
                const float d1 = kn[i + dg] - kn[i];
                const float d2 = kn[i + dg + 1] - kn[i + 1];
                float t1 = (d1 > 1e-10f) ? ((t - kn[i]) * (1.0f / d1)) * c[i] : 0.f;
                float t2 = (d2 > 1e-10f) ? ((kn[i + dg + 1] - t) * (1.0f / d2)) * c[i + 1] : 0.f;
                c[i] = t1 + t2;
            }
        }
    }
    float s = 0.f;
#pragma unroll
    for (int j = 0; j < 8; ++j) s = fmaf(c[j], cps[j], s);
    s *= rwv;
    return fminf(fmaxf(s, -10.f), 10.f);
}

// ===========================================================================
// Weight convert: fp32 -> fp16.
// ===========================================================================
__global__ void wsplit(const float4* __restrict__ w, uint2* __restrict__ h, int n4) {
    int i = blockIdx.x * blockDim.x + threadIdx.x;
    if (i >= n4) return;
    float4 v = w[i];
    h[i] = make_uint2(pack_h2(v.x, v.y), pack_h2(v.z, v.w));
}

// ===========================================================================
// LayerNorm: fp32 -> fp16. 1 row/block, D = 2048.
// ===========================================================================
__global__ void ln_kernel(const float* __restrict__ x, __half* __restrict__ y) {
    const int D = 2048;
    const float* xr = x + (size_t)blockIdx.x * D;
    float s = 0.f, q = 0.f;
#pragma unroll
    for (int it = 0; it < 2; ++it) {
        float4 v = *(const float4*)(xr + threadIdx.x * 4 + it * 1024);
        s += (v.x + v.y) + (v.z + v.w);
        q += v.x * v.x + v.y * v.y + v.z * v.z + v.w * v.w;
    }
#pragma unroll
    for (int o = 16; o > 0; o >>= 1) {
        s += __shfl_xor_sync(~0u, s, o);
        q += __shfl_xor_sync(~0u, q, o);
    }
    __shared__ float ss[8], qq[8], mu_s, inv_s;
    if ((threadIdx.x & 31) == 0) { ss[threadIdx.x >> 5] = s; qq[threadIdx.x >> 5] = q; }
    __syncthreads();
    if (threadIdx.x == 0) {
        float ts = 0.f, tq = 0.f;
#pragma unroll
        for (int i = 0; i < 8; ++i) { ts += ss[i]; tq += qq[i]; }
        float mu = ts * (1.f / D);
        mu_s = mu;
        inv_s = rsqrtf(tq * (1.f / D) - mu * mu + 1e-5f);
    }
    __syncthreads();
    const float mu = mu_s, inv = inv_s;
    const size_t rb = (size_t)blockIdx.x * D;
#pragma unroll
    for (int it = 0; it < 2; ++it) {
        int i = threadIdx.x * 4 + it * 1024;
        float4 v = *(const float4*)(xr + i);
        *(uint2*)(y + rb + i) =
            make_uint2(pack_h2((v.x - mu) * inv, (v.y - mu) * inv),
                       pack_h2((v.z - mu) * inv, (v.w - mu) * inv));
    }
}

// ===========================================================================
// GEMM via mma.sync m16n8k16 fp16, single product, fp32 accumulator.
// BM=BN=128, BK=32, 8 warps (warp tile 64x32), 3-stage cp.async,
// 80B-pitch rows -> conflict-free ldmatrix.
// KAN=1: bias + spline + pair transform -> fp16 out.
// KAN=0: bias -> fp32 out.
// SMEM: [0,5120) params; stage st at 5120+st*20480: {A, W} each 128 x 80 B.
// ===========================================================================
template <int KAN>
__global__ void __launch_bounds__(256, 1)
gemm_mma(const __half* __restrict__ A, const __half* __restrict__ Wh,
         const float* __restrict__ bias, const float* __restrict__ cp,
         const float* __restrict__ rw, float* __restrict__ Cf,
         __half* __restrict__ Ch, int N, int K) {
    extern __shared__ char smem[];
    float* smf = (float*)smem;
    const uint32_t sb = smem_u32(smem);
    constexpr uint32_t PARAMB = 5120, PLANE = 10240, STAGE = 20480;

    const int tid = threadIdx.x, lane = tid & 31, wid = tid >> 5;
    const int warp_m = wid & 1, warp_n = wid >> 1;
    const int row0 = blockIdx.y * 128, col0 = blockIdx.x * 128;

    for (int i = tid; i < 128; i += 256) {
        smf[i] = bias[col0 + i];
        if (KAN) smf[128 + i] = rw[col0 + i];
    }
    if (KAN)
        for (int i = tid; i < 1024; i += 256)
            smf[256 + i] = cp[(size_t)(col0 + (i >> 3)) * 9 + (i & 7)];

    // loader: 1024 x 16B per stage (2 planes x 128 rows x 4 chunks), 4/thread
    auto issue = [&](int kt, int st) {
#pragma unroll
        for (int i = 0; i < 4; ++i) {
            int id = tid + 256 * i;
            int plane = id >> 9;  // 0 = A, 1 = W
            int rem = id & 511;
            int r = rem >> 2, c16 = rem & 3;
            const __half* gp = plane ? Wh + (size_t)(col0 + r) * K + kt * 32 + c16 * 8
                                     : A + (size_t)(row0 + r) * K + kt * 32 + c16 * 8;
            uint32_t sa = sb + PARAMB + st * STAGE + plane * PLANE + r * 80 + c16 * 16;
            CP_ASYNC16(sa, gp);
        }
    };

    const int NC = K >> 5;
    issue(0, 0); CP_COMMIT();
    issue(1, 1); CP_COMMIT();

    float acc[4][4][4];
#pragma unroll
    for (int a = 0; a < 4; ++a)
#pragma unroll
        for (int b = 0; b < 4; ++b)
#pragma unroll
            for (int d = 0; d < 4; ++d) acc[a][b][d] = 0.f;

    uint32_t a_row[4], b_row[2];
#pragma unroll
    for (int mf = 0; mf < 4; ++mf)
        a_row[mf] = (uint32_t)(warp_m * 64 + mf * 16 + (lane & 15)) * 80;
#pragma unroll
    for (int nf2 = 0; nf2 < 2; ++nf2)
        b_row[nf2] =
            (uint32_t)(warp_n * 32 + nf2 * 16 + (lane & 7) + ((lane >> 4) & 1) * 8) * 80;
    const uint32_t a_koff = (uint32_t)(lane >> 4) * 16;
    const uint32_t b_koff = (uint32_t)((lane >> 3) & 1) * 16;

    for (int kt = 0; kt < NC; ++kt) {
        CP_WAIT1();
        __syncthreads();
        const int nx = kt + 2;
        if (nx < NC) issue(nx, nx % 3);
        CP_COMMIT();

        const uint32_t base = sb + PARAMB + (uint32_t)(kt % 3) * STAGE;
#pragma unroll
        for (int k16 = 0; k16 < 2; ++k16) {
            const uint32_t kb = (uint32_t)k16 * 32;
            uint32_t ah[4][4], bh[4][2];
#pragma unroll
            for (int nf2 = 0; nf2 < 2; ++nf2) {
                uint32_t r0, r1, r2, r3;
                LDMX4(r0, r1, r2, r3, base + PLANE + b_row[nf2] + kb + b_koff);
                bh[nf2 * 2][0] = r0; bh[nf2 * 2][1] = r1;
                bh[nf2 * 2 + 1][0] = r2; bh[nf2 * 2 + 1][1] = r3;
            }
#pragma unroll
            for (int mf = 0; mf < 4; ++mf)
                LDMX4(ah[mf][0], ah[mf][1], ah[mf][2], ah[mf][3],
                      base + a_row[mf] + kb + a_koff);
#pragma unroll
            for (int mf = 0; mf < 4; ++mf)
#pragma unroll
                for (int nf = 0; nf < 4; ++nf)
                    MMAF16(acc[mf][nf], ah[mf], bh[nf][0], bh[nf][1]);
        }
    }

    // ---- epilogue: generator g = lane & 3; g in {2,3} -> identity ----
    const int g = lane & 3;
    const float cA = (g < 2) ? 0.05f : 0.f;
    const float sgn = (g == 1) ? -1.f : 1.f;

#pragma unroll
    for (int nf = 0; nf < 4; ++nf) {
        const int cl = warp_n * 32 + nf * 8 + 2 * (lane & 3);
        const float b0 = smf[cl], b1 = smf[cl + 1];
        float rw0 = 0.f, rw1 = 0.f, cps0[8], cps1[8];
        if (KAN) {
            rw0 = smf[128 + cl];
            rw1 = smf[128 + cl + 1];
#pragma unroll
            for (int j = 0; j < 8; ++j) {
                cps0[j] = smf[256 + cl * 8 + j];
                cps1[j] = smf[256 + (cl + 1) * 8 + j];
            }
        }
#pragma unroll
        for (int mf = 0; mf < 4; ++mf) {
            const int m0 = row0 + warp_m * 64 + mf * 16 + (lane >> 2);
            float v0 = acc[mf][nf][0] + b0, v1 = acc[mf][nf][1] + b1;
            float v2 = acc[mf][nf][2] + b0, v3 = acc[mf][nf][3] + b1;
            if (KAN) {
                v0 = kan_eval(v0, cps0, rw0);
                v1 = kan_eval(v1, cps1, rw1);
                v2 = kan_eval(v2, cps0, rw0);
                v3 = kan_eval(v3, cps1, rw1);
                float t = v0;
                v0 = fmaf(cA, clip1f(sgn * v1), v0);
                v1 = fmaf(cA, clip1f(t), v1);
                t = v2;
                v2 = fmaf(cA, clip1f(sgn * v3), v2);
                v3 = fmaf(cA, clip1f(t), v3);
                const size_t i0 = (size_t)m0 * N + col0 + cl;
                const size_t i1 = (size_t)(m0 + 8) * N + col0 + cl;
                *(uint32_t*)(Ch + i0) = pack_h2(v0, v1);
                *(uint32_t*)(Ch + i1) = pack_h2(v2, v3);
            } else {
                const size_t i0 = (size_t)m0 * N + col0 + cl;
                const size_t i1 = (size_t)(m0 + 8) * N + col0 + cl;
                *(float2*)(Cf + i0) = make_float2(v0, v1);
                *(float2*)(Cf + i1) = make_float2(v2, v3);
            }
        }
    }
}

// ===========================================================================
// Launch
// ===========================================================================
static constexpr int SMEM_BYTES = 5120 + 3 * 20480;  // 66560

extern "C" void kernel_launch(void* const* d_in, const int* in_sizes, int n_in,
                              void* d_out, int out_size) {
    const float* x = (const float*)d_in[0];
    const float* W1 = (const float*)d_in[1];
    const float* b1 = (const float*)d_in[2];
    const float* cp1 = (const float*)d_in[3];
    const float* rw1 = (const float*)d_in[4];
    const float* W2 = (const float*)d_in[5];
    const float* b2 = (const float*)d_in[6];
    const float* cp2 = (const float*)d_in[7];
    const float* rw2 = (const float*)d_in[8];
    const float* W3 = (const float*)d_in[9];
    const float* b3 = (const float*)d_in[10];
    const float* cp3 = (const float*)d_in[11];
    const float* rw3 = (const float*)d_in[12];
    const float* Wo = (const float*)d_in[13];
    const float* bo = (const float*)d_in[14];

    static __half *A = nullptr, *B, *Wh;
    if (!A) {
        cudaGetSymbolAddress((void**)&A, g_A);
        cudaGetSymbolAddress((void**)&B, g_B);
        cudaGetSymbolAddress((void**)&Wh, g_Wh);
        cudaFuncSetAttribute(gemm_mma<1>, cudaFuncAttributeMaxDynamicSharedMemorySize, SMEM_BYTES);
        cudaFuncSetAttribute(gemm_mma<0>, cudaFuncAttributeMaxDynamicSharedMemorySize, SMEM_BYTES);
    }

    // ---- weight convert prepass ----
    wsplit<<<8388608 / 4 / 256, 256>>>((const float4*)W1, (uint2*)(Wh + W_OFF1), 8388608 / 4);
    wsplit<<<16777216 / 4 / 256, 256>>>((const float4*)W2, (uint2*)(Wh + W_OFF2), 16777216 / 4);
    wsplit<<<8388608 / 4 / 256, 256>>>((const float4*)W3, (uint2*)(Wh + W_OFF3), 8388608 / 4);
    wsplit<<<4194304 / 4 / 256, 256>>>((const float4*)Wo, (uint2*)(Wh + W_OFFO), 4194304 / 4);

    // ---- LN: x -> A fp16, K = 2048 ----
    ln_kernel<<<1024, 256>>>(x, A);

    // ---- GEMM chain ----
    gemm_mma<1><<<dim3(32, 8), 256, SMEM_BYTES>>>(A, Wh + W_OFF1, b1, cp1, rw1,
                                                  nullptr, B, 4096, 2048);
    gemm_mma<1><<<dim3(32, 8), 256, SMEM_BYTES>>>(B, Wh + W_OFF2, b2, cp2, rw2,
                                                  nullptr, A, 4096, 4096);
    gemm_mma<1><<<dim3(16, 8), 256, SMEM_BYTES>>>(A, Wh + W_OFF3, b3, cp3, rw3,
                                                  nullptr, B, 2048, 4096);
    gemm_mma<0><<<dim3(16, 8), 256, SMEM_BYTES>>>(B, Wh + W_OFFO, bo, nullptr,
                                                  nullptr, (float*)d_out, nullptr,
                                                  2048, 2048);
}

// round 11
// speedup vs baseline: 2.6244x; 1.1569x over previous
#include <cuda_runtime.h>
#include <cuda_fp16.h>
#include <cstdint>

// ===========================================================================
// Scratch (static __device__ globals — no runtime allocation).
// Activations: single fp16 plane ping-pong. Weights: single fp16 plane.
// ===========================================================================
__device__ __half g_A[1024 * 4096];
__device__ __half g_B[1024 * 4096];
__device__ __half g_Wh[37748736];

static const size_t W_OFF1 = 0;
static const size_t W_OFF2 = 8388608;
static const size_t W_OFF3 = 25165824;
static const size_t W_OFFO = 33554432;

// ===========================================================================
// PTX helpers (sm_80-era, valid on plain compute_103)
// ===========================================================================
__device__ __forceinline__ uint32_t smem_u32(const void* p) {
    uint32_t a;
    asm("{ .reg .u64 t; cvta.to.shared.u64 t, %1; cvt.u32.u64 %0, t; }" : "=r"(a) : "l"(p));
    return a;
}
#define CP_ASYNC16(sa, ga) \
    asm volatile("cp.async.cg.shared.global [%0], [%1], 16;" ::"r"(sa), "l"(ga) : "memory")
#define CP_COMMIT() asm volatile("cp.async.commit_group;" ::: "memory")
#define CP_WAIT1() asm volatile("cp.async.wait_group 1;" ::: "memory")

#define LDMX4(r0, r1, r2, r3, addr)                                              \
    asm volatile("ldmatrix.sync.aligned.m8n8.x4.shared.b16 {%0,%1,%2,%3}, [%4];" \
                 : "=r"(r0), "=r"(r1), "=r"(r2), "=r"(r3) : "r"(addr))

#define MMAF16(c, a, b0, b1)                                                    \
    asm volatile(                                                               \
        "mma.sync.aligned.m16n8k16.row.col.f32.f16.f16.f32 "                    \
        "{%0,%1,%2,%3}, {%4,%5,%6,%7}, {%8,%9}, {%0,%1,%2,%3};"                 \
        : "+f"((c)[0]), "+f"((c)[1]), "+f"((c)[2]), "+f"((c)[3])                \
        : "r"((a)[0]), "r"((a)[1]), "r"((a)[2]), "r"((a)[3]), "r"(b0), "r"(b1))

__device__ __forceinline__ uint32_t pack_h2(float a, float b) {
    __half2 t = __floats2half2_rn(a, b);
    return *reinterpret_cast<uint32_t*>(&t);
}
__device__ __forceinline__ float clip1f(float x) { return fminf(fmaxf(x, -1.f), 1.f); }

// ---------------------------------------------------------------------------
// KAN activation (constant-folded partial Cox-de Boor; validated R4/R6/R9/R10).
// ---------------------------------------------------------------------------
__device__ __forceinline__ float kan_eval(float x, const float* __restrict__ cps, float rwv) {
    float t = tanhf(x);
    const float kn[12] = {-1.f, -1.f, -1.f, -1.f, -0.6f, -0.2f, 0.2f, 0.6f, 1.f, 1.f, 1.f, 1.f};
    float c[8];
#pragma unroll
    for (int i = 0; i < 8; ++i) c[i] = (t >= kn[i] && t < kn[i + 1]) ? 1.f : 0.f;
#pragma unroll
    for (int dg = 1; dg <= 3; ++dg) {
#pragma unroll
        for (int i = 0; i < 7; ++i) {
            if (i < 8 - dg) {
                const float d1 = kn[i + dg] - kn[i];
                const float d2 = kn[i + dg + 1] - kn[i + 1];
                float t1 = (d1 > 1e-10f) ? ((t - kn[i]) * (1.0f / d1)) * c[i] : 0.f;
                float t2 = (d2 > 1e-10f) ? ((kn[i + dg + 1] - t) * (1.0f / d2)) * c[i + 1] : 0.f;
                c[i] = t1 + t2;
            }
        }
    }
    float s = 0.f;
#pragma unroll
    for (int j = 0; j < 8; ++j) s = fmaf(c[j], cps[j], s);
    s *= rwv;
    return fminf(fmaxf(s, -10.f), 10.f);
}

// ===========================================================================
// Weight convert: fp32 -> fp16.
// ===========================================================================
__global__ void wsplit(const float4* __restrict__ w, uint2* __restrict__ h, int n4) {
    int i = blockIdx.x * blockDim.x + threadIdx.x;
    if (i >= n4) return;
    float4 v = w[i];
    h[i] = make_uint2(pack_h2(v.x, v.y), pack_h2(v.z, v.w));
}

// ===========================================================================
// LayerNorm: fp32 -> fp16. 1 row/block, D = 2048.
// ===========================================================================
__global__ void ln_kernel(const float* __restrict__ x, __half* __restrict__ y) {
    const int D = 2048;
    const float* xr = x + (size_t)blockIdx.x * D;
    float s = 0.f, q = 0.f;
#pragma unroll
    for (int it = 0; it < 2; ++it) {
        float4 v = *(const float4*)(xr + threadIdx.x * 4 + it * 1024);
        s += (v.x + v.y) + (v.z + v.w);
        q += v.x * v.x + v.y * v.y + v.z * v.z + v.w * v.w;
    }
#pragma unroll
    for (int o = 16; o > 0; o >>= 1) {
        s += __shfl_xor_sync(~0u, s, o);
        q += __shfl_xor_sync(~0u, q, o);
    }
    __shared__ float ss[8], qq[8], mu_s, inv_s;
    if ((threadIdx.x & 31) == 0) { ss[threadIdx.x >> 5] = s; qq[threadIdx.x >> 5] = q; }
    __syncthreads();
    if (threadIdx.x == 0) {
        float ts = 0.f, tq = 0.f;
#pragma unroll
        for (int i = 0; i < 8; ++i) { ts += ss[i]; tq += qq[i]; }
        float mu = ts * (1.f / D);
        mu_s = mu;
        inv_s = rsqrtf(tq * (1.f / D) - mu * mu + 1e-5f);
    }
    __syncthreads();
    const float mu = mu_s, inv = inv_s;
    const size_t rb = (size_t)blockIdx.x * D;
#pragma unroll
    for (int it = 0; it < 2; ++it) {
        int i = threadIdx.x * 4 + it * 1024;
        float4 v = *(const float4*)(xr + i);
        *(uint2*)(y + rb + i) =
            make_uint2(pack_h2((v.x - mu) * inv, (v.y - mu) * inv),
                       pack_h2((v.z - mu) * inv, (v.w - mu) * inv));
    }
}

// ===========================================================================
// GEMM via mma.sync m16n8k16 fp16, single product, fp32 accumulator.
// BM=BN=128, BK=32, 8 warps (warp tile 64x32), 3-stage cp.async,
// 80B-pitch rows -> conflict-free ldmatrix. 2 CTAs/SM co-residency:
// one CTA's MMA bursts cover the other's cp.async-wait / sync / epilogue.
// KAN=1: bias + spline + pair transform -> fp16 out.
// KAN=0: bias -> fp32 out.
// SMEM: [0,5120) params; stage st at 5120+st*20480: {A, W} each 128 x 80 B.
// ===========================================================================
template <int KAN>
__global__ void __launch_bounds__(256, 2)
gemm_mma(const __half* __restrict__ A, const __half* __restrict__ Wh,
         const float* __restrict__ bias, const float* __restrict__ cp,
         const float* __restrict__ rw, float* __restrict__ Cf,
         __half* __restrict__ Ch, int N, int K) {
    extern __shared__ char smem[];
    float* smf = (float*)smem;
    const uint32_t sb = smem_u32(smem);
    constexpr uint32_t PARAMB = 5120, PLANE = 10240, STAGE = 20480;

    const int tid = threadIdx.x, lane = tid & 31, wid = tid >> 5;
    const int warp_m = wid & 1, warp_n = wid >> 1;
    const int row0 = blockIdx.y * 128, col0 = blockIdx.x * 128;

    for (int i = tid; i < 128; i += 256) {
        smf[i] = bias[col0 + i];
        if (KAN) smf[128 + i] = rw[col0 + i];
    }
    if (KAN)
        for (int i = tid; i < 1024; i += 256)
            smf[256 + i] = cp[(size_t)(col0 + (i >> 3)) * 9 + (i & 7)];

    // loader: 1024 x 16B per stage (2 planes x 128 rows x 4 chunks), 4/thread
    auto issue = [&](int kt, int st) {
#pragma unroll
        for (int i = 0; i < 4; ++i) {
            int id = tid + 256 * i;
            int plane = id >> 9;  // 0 = A, 1 = W
            int rem = id & 511;
            int r = rem >> 2, c16 = rem & 3;
            const __half* gp = plane ? Wh + (size_t)(col0 + r) * K + kt * 32 + c16 * 8
                                     : A + (size_t)(row0 + r) * K + kt * 32 + c16 * 8;
            uint32_t sa = sb + PARAMB + st * STAGE + plane * PLANE + r * 80 + c16 * 16;
            CP_ASYNC16(sa, gp);
        }
    };

    const int NC = K >> 5;
    issue(0, 0); CP_COMMIT();
    issue(1, 1); CP_COMMIT();

    float acc[4][4][4];
#pragma unroll
    for (int a = 0; a < 4; ++a)
#pragma unroll
        for (int b = 0; b < 4; ++b)
#pragma unroll
            for (int d = 0; d < 4; ++d) acc[a][b][d] = 0.f;

    uint32_t a_row[4], b_row[2];
#pragma unroll
    for (int mf = 0; mf < 4; ++mf)
        a_row[mf] = (uint32_t)(warp_m * 64 + mf * 16 + (lane & 15)) * 80;
#pragma unroll
    for (int nf2 = 0; nf2 < 2; ++nf2)
        b_row[nf2] =
            (uint32_t)(warp_n * 32 + nf2 * 16 + (lane & 7) + ((lane >> 4) & 1) * 8) * 80;
    const uint32_t a_koff = (uint32_t)(lane >> 4) * 16;
    const uint32_t b_koff = (uint32_t)((lane >> 3) & 1) * 16;

    for (int kt = 0; kt < NC; ++kt) {
        CP_WAIT1();
        __syncthreads();
        const int nx = kt + 2;
        if (nx < NC) issue(nx, nx % 3);
        CP_COMMIT();

        const uint32_t base = sb + PARAMB + (uint32_t)(kt % 3) * STAGE;
#pragma unroll
        for (int k16 = 0; k16 < 2; ++k16) {
            const uint32_t kb = (uint32_t)k16 * 32;
            uint32_t ah[4][4], bh[4][2];
#pragma unroll
            for (int nf2 = 0; nf2 < 2; ++nf2) {
                uint32_t r0, r1, r2, r3;
                LDMX4(r0, r1, r2, r3, base + PLANE + b_row[nf2] + kb + b_koff);
                bh[nf2 * 2][0] = r0; bh[nf2 * 2][1] = r1;
                bh[nf2 * 2 + 1][0] = r2; bh[nf2 * 2 + 1][1] = r3;
            }
#pragma unroll
            for (int mf = 0; mf < 4; ++mf)
                LDMX4(ah[mf][0], ah[mf][1], ah[mf][2], ah[mf][3],
                      base + a_row[mf] + kb + a_koff);
#pragma unroll
            for (int mf = 0; mf < 4; ++mf)
#pragma unroll
                for (int nf = 0; nf < 4; ++nf)
                    MMAF16(acc[mf][nf], ah[mf], bh[nf][0], bh[nf][1]);
        }
    }

    // ---- epilogue: generator g = lane & 3; g in {2,3} -> identity ----
    const int g = lane & 3;
    const float cA = (g < 2) ? 0.05f : 0.f;
    const float sgn = (g == 1) ? -1.f : 1.f;

#pragma unroll
    for (int nf = 0; nf < 4; ++nf) {
        const int cl = warp_n * 32 + nf * 8 + 2 * (lane & 3);
        const float b0 = smf[cl], b1 = smf[cl + 1];
        float rw0 = 0.f, rw1 = 0.f, cps0[8], cps1[8];
        if (KAN) {
            rw0 = smf[128 + cl];
            rw1 = smf[128 + cl + 1];
#pragma unroll
            for (int j = 0; j < 8; ++j) {
                cps0[j] = smf[256 + cl * 8 + j];
                cps1[j] = smf[256 + (cl + 1) * 8 + j];
            }
        }
#pragma unroll
        for (int mf = 0; mf < 4; ++mf) {
            const int m0 = row0 + warp_m * 64 + mf * 16 + (lane >> 2);
            float v0 = acc[mf][nf][0] + b0, v1 = acc[mf][nf][1] + b1;
            float v2 = acc[mf][nf][2] + b0, v3 = acc[mf][nf][3] + b1;
            if (KAN) {
                v0 = kan_eval(v0, cps0, rw0);
                v1 = kan_eval(v1, cps1, rw1);
                v2 = kan_eval(v2, cps0, rw0);
                v3 = kan_eval(v3, cps1, rw1);
                float t = v0;
                v0 = fmaf(cA, clip1f(sgn * v1), v0);
                v1 = fmaf(cA, clip1f(t), v1);
                t = v2;
                v2 = fmaf(cA, clip1f(sgn * v3), v2);
                v3 = fmaf(cA, clip1f(t), v3);
                const size_t i0 = (size_t)m0 * N + col0 + cl;
                const size_t i1 = (size_t)(m0 + 8) * N + col0 + cl;
                *(uint32_t*)(Ch + i0) = pack_h2(v0, v1);
                *(uint32_t*)(Ch + i1) = pack_h2(v2, v3);
            } else {
                const size_t i0 = (size_t)m0 * N + col0 + cl;
                const size_t i1 = (size_t)(m0 + 8) * N + col0 + cl;
                *(float2*)(Cf + i0) = make_float2(v0, v1);
                *(float2*)(Cf + i1) = make_float2(v2, v3);
            }
        }
    }
}

// ===========================================================================
// Launch
// ===========================================================================
static constexpr int SMEM_BYTES = 5120 + 3 * 20480;  // 66560 (x2 CTAs = 133KB/SM)

extern "C" void kernel_launch(void* const* d_in, const int* in_sizes, int n_in,
                              void* d_out, int out_size) {
    const float* x = (const float*)d_in[0];
    const float* W1 = (const float*)d_in[1];
    const float* b1 = (const float*)d_in[2];
    const float* cp1 = (const float*)d_in[3];
    const float* rw1 = (const float*)d_in[4];
    const float* W2 = (const float*)d_in[5];
    const float* b2 = (const float*)d_in[6];
    const float* cp2 = (const float*)d_in[7];
    const float* rw2 = (const float*)d_in[8];
    const float* W3 = (const float*)d_in[9];
    const float* b3 = (const float*)d_in[10];
    const float* cp3 = (const float*)d_in[11];
    const float* rw3 = (const float*)d_in[12];
    const float* Wo = (const float*)d_in[13];
    const float* bo = (const float*)d_in[14];

    static __half *A = nullptr, *B, *Wh;
    if (!A) {
        cudaGetSymbolAddress((void**)&A, g_A);
        cudaGetSymbolAddress((void**)&B, g_B);
        cudaGetSymbolAddress((void**)&Wh, g_Wh);
        cudaFuncSetAttribute(gemm_mma<1>, cudaFuncAttributeMaxDynamicSharedMemorySize, SMEM_BYTES);
        cudaFuncSetAttribute(gemm_mma<0>, cudaFuncAttributeMaxDynamicSharedMemorySize, SMEM_BYTES);
    }

    // ---- weight convert prepass ----
    wsplit<<<8388608 / 4 / 256, 256>>>((const float4*)W1, (uint2*)(Wh + W_OFF1), 8388608 / 4);
    wsplit<<<16777216 / 4 / 256, 256>>>((const float4*)W2, (uint2*)(Wh + W_OFF2), 16777216 / 4);
    wsplit<<<8388608 / 4 / 256, 256>>>((const float4*)W3, (uint2*)(Wh + W_OFF3), 8388608 / 4);
    wsplit<<<4194304 / 4 / 256, 256>>>((const float4*)Wo, (uint2*)(Wh + W_OFFO), 4194304 / 4);

    // ---- LN: x -> A fp16, K = 2048 ----
    ln_kernel<<<1024, 256>>>(x, A);

    // ---- GEMM chain ----
    gemm_mma<1><<<dim3(32, 8), 256, SMEM_BYTES>>>(A, Wh + W_OFF1, b1, cp1, rw1,
                                                  nullptr, B, 4096, 2048);
    gemm_mma<1><<<dim3(32, 8), 256, SMEM_BYTES>>>(B, Wh + W_OFF2, b2, cp2, rw2,
                                                  nullptr, A, 4096, 4096);
    gemm_mma<1><<<dim3(16, 8), 256, SMEM_BYTES>>>(A, Wh + W_OFF3, b3, cp3, rw3,
                                                  nullptr, B, 2048, 4096);
    gemm_mma<0><<<dim3(16, 8), 256, SMEM_BYTES>>>(B, Wh + W_OFFO, bo, nullptr,
                                                  nullptr, (float*)d_out, nullptr,
                                                  2048, 2048);
}

// round 12
// speedup vs baseline: 2.6578x; 1.0127x over previous
#include <cuda_runtime.h>
#include <cuda_fp16.h>
#include <cstdint>

// ===========================================================================
// Scratch (static __device__ globals — no runtime allocation).
// Activations: single fp16 plane ping-pong. Weights: single fp16 plane.
// ===========================================================================
__device__ __half g_A[1024 * 4096];
__device__ __half g_B[1024 * 4096];
__device__ __half g_Wh[37748736];

static const size_t W_OFF1 = 0;
static const size_t W_OFF2 = 8388608;
static const size_t W_OFF3 = 25165824;
static const size_t W_OFFO = 33554432;

// ===========================================================================
// PTX helpers (sm_80-era, valid on plain compute_103)
// ===========================================================================
__device__ __forceinline__ uint32_t smem_u32(const void* p) {
    uint32_t a;
    asm("{ .reg .u64 t; cvta.to.shared.u64 t, %1; cvt.u32.u64 %0, t; }" : "=r"(a) : "l"(p));
    return a;
}
#define CP_ASYNC16(sa, ga) \
    asm volatile("cp.async.cg.shared.global [%0], [%1], 16;" ::"r"(sa), "l"(ga) : "memory")
#define CP_COMMIT() asm volatile("cp.async.commit_group;" ::: "memory")
#define CP_WAIT1() asm volatile("cp.async.wait_group 1;" ::: "memory")

#define LDMX4(r0, r1, r2, r3, addr)                                              \
    asm volatile("ldmatrix.sync.aligned.m8n8.x4.shared.b16 {%0,%1,%2,%3}, [%4];" \
                 : "=r"(r0), "=r"(r1), "=r"(r2), "=r"(r3) : "r"(addr))

#define MMAF16(c, a, b0, b1)                                                    \
    asm volatile(                                                               \
        "mma.sync.aligned.m16n8k16.row.col.f32.f16.f16.f32 "                    \
        "{%0,%1,%2,%3}, {%4,%5,%6,%7}, {%8,%9}, {%0,%1,%2,%3};"                 \
        : "+f"((c)[0]), "+f"((c)[1]), "+f"((c)[2]), "+f"((c)[3])                \
        : "r"((a)[0]), "r"((a)[1]), "r"((a)[2]), "r"((a)[3]), "r"(b0), "r"(b1))

__device__ __forceinline__ uint32_t pack_h2(float a, float b) {
    __half2 t = __floats2half2_rn(a, b);
    return *reinterpret_cast<uint32_t*>(&t);
}
__device__ __forceinline__ float clip1f(float x) { return fminf(fmaxf(x, -1.f), 1.f); }

// ---------------------------------------------------------------------------
// KAN activation (constant-folded partial Cox-de Boor; validated R4..R11).
// ---------------------------------------------------------------------------
__device__ __forceinline__ float kan_eval(float x, const float* __restrict__ cps, float rwv) {
    float t = tanhf(x);
    const float kn[12] = {-1.f, -1.f, -1.f, -1.f, -0.6f, -0.2f, 0.2f, 0.6f, 1.f, 1.f, 1.f, 1.f};
    float c[8];
#pragma unroll
    for (int i = 0; i < 8; ++i) c[i] = (t >= kn[i] && t < kn[i + 1]) ? 1.f : 0.f;
#pragma unroll
    for (int dg = 1; dg <= 3; ++dg) {
#pragma unroll
        for (int i = 0; i < 7; ++i) {
            if (i < 8 - dg) {
                const float d1 = kn[i + dg] - kn[i];
                const float d2 = kn[i + dg + 1] - kn[i + 1];
                float t1 = (d1 > 1e-10f) ? ((t - kn[i]) * (1.0f / d1)) * c[i] : 0.f;
                float t2 = (d2 > 1e-10f) ? ((kn[i + dg + 1] - t) * (1.0f / d2)) * c[i + 1] : 0.f;
                c[i] = t1 + t2;
            }
        }
    }
    float s = 0.f;
#pragma unroll
    for (int j = 0; j < 8; ++j) s = fmaf(c[j], cps[j], s);
    s *= rwv;
    return fminf(fmaxf(s, -10.f), 10.f);
}

// ===========================================================================
// Weight convert: fp32 -> fp16.
// ===========================================================================
__global__ void wsplit(const float4* __restrict__ w, uint2* __restrict__ h, int n4) {
    int i = blockIdx.x * blockDim.x + threadIdx.x;
    if (i >= n4) return;
    float4 v = w[i];
    h[i] = make_uint2(pack_h2(v.x, v.y), pack_h2(v.z, v.w));
}

// ===========================================================================
// LayerNorm: fp32 -> fp16. 1 row/block, D = 2048.
// ===========================================================================
__global__ void ln_kernel(const float* __restrict__ x, __half* __restrict__ y) {
    const int D = 2048;
    const float* xr = x + (size_t)blockIdx.x * D;
    float s = 0.f, q = 0.f;
#pragma unroll
    for (int it = 0; it < 2; ++it) {
        float4 v = *(const float4*)(xr + threadIdx.x * 4 + it * 1024);
        s += (v.x + v.y) + (v.z + v.w);
        q += v.x * v.x + v.y * v.y + v.z * v.z + v.w * v.w;
    }
#pragma unroll
    for (int o = 16; o > 0; o >>= 1) {
        s += __shfl_xor_sync(~0u, s, o);
        q += __shfl_xor_sync(~0u, q, o);
    }
    __shared__ float ss[8], qq[8], mu_s, inv_s;
    if ((threadIdx.x & 31) == 0) { ss[threadIdx.x >> 5] = s; qq[threadIdx.x >> 5] = q; }
    __syncthreads();
    if (threadIdx.x == 0) {
        float ts = 0.f, tq = 0.f;
#pragma unroll
        for (int i = 0; i < 8; ++i) { ts += ss[i]; tq += qq[i]; }
        float mu = ts * (1.f / D);
        mu_s = mu;
        inv_s = rsqrtf(tq * (1.f / D) - mu * mu + 1e-5f);
    }
    __syncthreads();
    const float mu = mu_s, inv = inv_s;
    const size_t rb = (size_t)blockIdx.x * D;
#pragma unroll
    for (int it = 0; it < 2; ++it) {
        int i = threadIdx.x * 4 + it * 1024;
        float4 v = *(const float4*)(xr + i);
        *(uint2*)(y + rb + i) =
            make_uint2(pack_h2((v.x - mu) * inv, (v.y - mu) * inv),
                       pack_h2((v.z - mu) * inv, (v.w - mu) * inv));
    }
}

// ===========================================================================
// GEMM via mma.sync m16n8k16 fp16, single product, fp32 accumulator.
// BM=BN=128, BK=32, 8 warps (warp tile 64x32), 3-stage cp.async,
// 80B-pitch rows -> conflict-free ldmatrix. 2 CTAs/SM co-residency.
// KAN=1: bias + spline + pair transform -> fp16 out.  KAN=0: fp32 out.
// SMEM: [0,5120) params; stage st at 5120+st*20480: {A, W} each 128 x 80 B.
// ===========================================================================
template <int KAN>
__global__ void __launch_bounds__(256, 2)
gemm_mma(const __half* __restrict__ A, const __half* __restrict__ Wh,
         const float* __restrict__ bias, const float* __restrict__ cp,
         const float* __restrict__ rw, float* __restrict__ Cf,
         __half* __restrict__ Ch, int N, int K) {
    extern __shared__ char smem[];
    float* smf = (float*)smem;
    const uint32_t sb = smem_u32(smem);
    constexpr uint32_t PARAMB = 5120, PLANE = 10240, STAGE = 20480;

    const int tid = threadIdx.x, lane = tid & 31, wid = tid >> 5;
    const int warp_m = wid & 1, warp_n = wid >> 1;
    const int row0 = blockIdx.y * 128, col0 = blockIdx.x * 128;

    for (int i = tid; i < 128; i += 256) {
        smf[i] = bias[col0 + i];
        if (KAN) smf[128 + i] = rw[col0 + i];
    }
    if (KAN)
        for (int i = tid; i < 1024; i += 256)
            smf[256 + i] = cp[(size_t)(col0 + (i >> 3)) * 9 + (i & 7)];

    // loader: 1024 x 16B per stage (2 planes x 128 rows x 4 chunks), 4/thread
    auto issue = [&](int kt, int st) {
#pragma unroll
        for (int i = 0; i < 4; ++i) {
            int id = tid + 256 * i;
            int plane = id >> 9;  // 0 = A, 1 = W
            int rem = id & 511;
            int r = rem >> 2, c16 = rem & 3;
            const __half* gp = plane ? Wh + (size_t)(col0 + r) * K + kt * 32 + c16 * 8
                                     : A + (size_t)(row0 + r) * K + kt * 32 + c16 * 8;
            uint32_t sa = sb + PARAMB + st * STAGE + plane * PLANE + r * 80 + c16 * 16;
            CP_ASYNC16(sa, gp);
        }
    };

    const int NC = K >> 5;
    issue(0, 0); CP_COMMIT();
    issue(1, 1); CP_COMMIT();

    float acc[4][4][4];
#pragma unroll
    for (int a = 0; a < 4; ++a)
#pragma unroll
        for (int b = 0; b < 4; ++b)
#pragma unroll
            for (int d = 0; d < 4; ++d) acc[a][b][d] = 0.f;

    uint32_t a_row[4], b_row[2];
#pragma unroll
    for (int mf = 0; mf < 4; ++mf)
        a_row[mf] = (uint32_t)(warp_m * 64 + mf * 16 + (lane & 15)) * 80;
#pragma unroll
    for (int nf2 = 0; nf2 < 2; ++nf2)
        b_row[nf2] =
            (uint32_t)(warp_n * 32 + nf2 * 16 + (lane & 7) + ((lane >> 4) & 1) * 8) * 80;
    const uint32_t a_koff = (uint32_t)(lane >> 4) * 16;
    const uint32_t b_koff = (uint32_t)((lane >> 3) & 1) * 16;

    for (int kt = 0; kt < NC; ++kt) {
        CP_WAIT1();
        __syncthreads();
        const int nx = kt + 2;
        if (nx < NC) issue(nx, nx % 3);
        CP_COMMIT();

        const uint32_t base = sb + PARAMB + (uint32_t)(kt % 3) * STAGE;
#pragma unroll
        for (int k16 = 0; k16 < 2; ++k16) {
            const uint32_t kb = (uint32_t)k16 * 32;
            uint32_t ah[4][4], bh[4][2];
#pragma unroll
            for (int nf2 = 0; nf2 < 2; ++nf2) {
                uint32_t r0, r1, r2, r3;
                LDMX4(r0, r1, r2, r3, base + PLANE + b_row[nf2] + kb + b_koff);
                bh[nf2 * 2][0] = r0; bh[nf2 * 2][1] = r1;
                bh[nf2 * 2 + 1][0] = r2; bh[nf2 * 2 + 1][1] = r3;
            }
#pragma unroll
            for (int mf = 0; mf < 4; ++mf)
                LDMX4(ah[mf][0], ah[mf][1], ah[mf][2], ah[mf][3],
                      base + a_row[mf] + kb + a_koff);
#pragma unroll
            for (int mf = 0; mf < 4; ++mf)
#pragma unroll
                for (int nf = 0; nf < 4; ++nf)
                    MMAF16(acc[mf][nf], ah[mf], bh[nf][0], bh[nf][1]);
        }
    }

    // ---- epilogue: generator g = lane & 3; g in {2,3} -> identity ----
    const int g = lane & 3;
    const float cA = (g < 2) ? 0.05f : 0.f;
    const float sgn = (g == 1) ? -1.f : 1.f;

#pragma unroll
    for (int nf = 0; nf < 4; ++nf) {
        const int cl = warp_n * 32 + nf * 8 + 2 * (lane & 3);
        const float b0 = smf[cl], b1 = smf[cl + 1];
        float rw0 = 0.f, rw1 = 0.f, cps0[8], cps1[8];
        if (KAN) {
            rw0 = smf[128 + cl];
            rw1 = smf[128 + cl + 1];
#pragma unroll
            for (int j = 0; j < 8; ++j) {
                cps0[j] = smf[256 + cl * 8 + j];
                cps1[j] = smf[256 + (cl + 1) * 8 + j];
            }
        }
#pragma unroll
        for (int mf = 0; mf < 4; ++mf) {
            const int m0 = row0 + warp_m * 64 + mf * 16 + (lane >> 2);
            float v0 = acc[mf][nf][0] + b0, v1 = acc[mf][nf][1] + b1;
            float v2 = acc[mf][nf][2] + b0, v3 = acc[mf][nf][3] + b1;
            if (KAN) {
                v0 = kan_eval(v0, cps0, rw0);
                v1 = kan_eval(v1, cps1, rw1);
                v2 = kan_eval(v2, cps0, rw0);
                v3 = kan_eval(v3, cps1, rw1);
                float t = v0;
                v0 = fmaf(cA, clip1f(sgn * v1), v0);
                v1 = fmaf(cA, clip1f(t), v1);
                t = v2;
                v2 = fmaf(cA, clip1f(sgn * v3), v2);
                v3 = fmaf(cA, clip1f(t), v3);
                const size_t i0 = (size_t)m0 * N + col0 + cl;
                const size_t i1 = (size_t)(m0 + 8) * N + col0 + cl;
                *(uint32_t*)(Ch + i0) = pack_h2(v0, v1);
                *(uint32_t*)(Ch + i1) = pack_h2(v2, v3);
            } else {
                const size_t i0 = (size_t)m0 * N + col0 + cl;
                const size_t i1 = (size_t)(m0 + 8) * N + col0 + cl;
                *(float2*)(Cf + i0) = make_float2(v0, v1);
                *(float2*)(Cf + i1) = make_float2(v2, v3);
            }
        }
    }
}

// ===========================================================================
// Launch. Side stream carries wsplit(W2,W3,Wo), overlapped with
// wsplit(W1)+LN+GEMM1 on the main stream; fork/join via events so the
// whole thing stays inside one capture graph.
// ===========================================================================
static constexpr int SMEM_BYTES = 5120 + 3 * 20480;  // 66560 (x2 CTAs = 133KB/SM)

extern "C" void kernel_launch(void* const* d_in, const int* in_sizes, int n_in,
                              void* d_out, int out_size) {
    const float* x = (const float*)d_in[0];
    const float* W1 = (const float*)d_in[1];
    const float* b1 = (const float*)d_in[2];
    const float* cp1 = (const float*)d_in[3];
    const float* rw1 = (const float*)d_in[4];
    const float* W2 = (const float*)d_in[5];
    const float* b2 = (const float*)d_in[6];
    const float* cp2 = (const float*)d_in[7];
    const float* rw2 = (const float*)d_in[8];
    const float* W3 = (const float*)d_in[9];
    const float* b3 = (const float*)d_in[10];
    const float* cp3 = (const float*)d_in[11];
    const float* rw3 = (const float*)d_in[12];
    const float* Wo = (const float*)d_in[13];
    const float* bo = (const float*)d_in[14];

    static __half *A = nullptr, *B, *Wh;
    static cudaStream_t s_side = nullptr;
    static cudaEvent_t ev_fork = nullptr, ev_join = nullptr;
    if (!A) {
        cudaGetSymbolAddress((void**)&A, g_A);
        cudaGetSymbolAddress((void**)&B, g_B);
        cudaGetSymbolAddress((void**)&Wh, g_Wh);
        cudaFuncSetAttribute(gemm_mma<1>, cudaFuncAttributeMaxDynamicSharedMemorySize, SMEM_BYTES);
        cudaFuncSetAttribute(gemm_mma<0>, cudaFuncAttributeMaxDynamicSharedMemorySize, SMEM_BYTES);
        cudaStreamCreateWithFlags(&s_side, cudaStreamNonBlocking);
        cudaEventCreateWithFlags(&ev_fork, cudaEventDisableTiming);
        cudaEventCreateWithFlags(&ev_join, cudaEventDisableTiming);
    }

    // ---- fork: side stream converts W2/W3/Wo while main runs W1+LN+GEMM1 ----
    cudaEventRecord(ev_fork, 0);
    cudaStreamWaitEvent(s_side, ev_fork, 0);
    wsplit<<<16777216 / 4 / 256, 256, 0, s_side>>>((const float4*)W2,
                                                   (uint2*)(Wh + W_OFF2), 16777216 / 4);
    wsplit<<<8388608 / 4 / 256, 256, 0, s_side>>>((const float4*)W3,
                                                  (uint2*)(Wh + W_OFF3), 8388608 / 4);
    wsplit<<<4194304 / 4 / 256, 256, 0, s_side>>>((const float4*)Wo,
                                                  (uint2*)(Wh + W_OFFO), 4194304 / 4);
    cudaEventRecord(ev_join, s_side);

    // ---- main stream: W1 convert + LN + GEMM1 ----
    wsplit<<<8388608 / 4 / 256, 256>>>((const float4*)W1, (uint2*)(Wh + W_OFF1), 8388608 / 4);
    ln_kernel<<<1024, 256>>>(x, A);
    gemm_mma<1><<<dim3(32, 8), 256, SMEM_BYTES>>>(A, Wh + W_OFF1, b1, cp1, rw1,
                                                  nullptr, B, 4096, 2048);

    // ---- join before GEMM2 needs W2 ----
    cudaStreamWaitEvent(0, ev_join, 0);

    gemm_mma<1><<<dim3(32, 8), 256, SMEM_BYTES>>>(B, Wh + W_OFF2, b2, cp2, rw2,
                                                  nullptr, A, 4096, 4096);
    gemm_mma<1><<<dim3(16, 8), 256, SMEM_BYTES>>>(A, Wh + W_OFF3, b3, cp3, rw3,
                                                  nullptr, B, 2048, 4096);
    gemm_mma<0><<<dim3(16, 8), 256, SMEM_BYTES>>>(B, Wh + W_OFFO, bo, nullptr,
                                                  nullptr, (float*)d_out, nullptr,
                                                  2048, 2048);
}

// round 16
// speedup vs baseline: 2.6711x; 1.0050x over previous
#include <cuda_runtime.h>
#include <cuda_fp16.h>
#include <cstdint>

// ===========================================================================
// Scratch (static __device__ globals — no runtime allocation).
// ===========================================================================
__device__ __half g_A[1024 * 4096];
__device__ __half g_B[1024 * 4096];
__device__ __half g_Wh[37748736];

static const size_t W_OFF1 = 0;
static const size_t W_OFF2 = 8388608;
static const size_t W_OFF3 = 25165824;
static const size_t W_OFFO = 33554432;

// ===========================================================================
// PTX helpers (sm_80-era, valid on plain compute_103)
// ===========================================================================
__device__ __forceinline__ uint32_t smem_u32(const void* p) {
    uint32_t a;
    asm("{ .reg .u64 t; cvta.to.shared.u64 t, %1; cvt.u32.u64 %0, t; }" : "=r"(a) : "l"(p));
    return a;
}
#define CP_ASYNC16(sa, ga) \
    asm volatile("cp.async.cg.shared.global [%0], [%1], 16;" ::"r"(sa), "l"(ga) : "memory")
#define CP_COMMIT() asm volatile("cp.async.commit_group;" ::: "memory")
#define CP_WAIT1() asm volatile("cp.async.wait_group 1;" ::: "memory")

#define LDMX4(r0, r1, r2, r3, addr)                                              \
    asm volatile("ldmatrix.sync.aligned.m8n8.x4.shared.b16 {%0,%1,%2,%3}, [%4];" \
                 : "=r"(r0), "=r"(r1), "=r"(r2), "=r"(r3) : "r"(addr))

#define MMAF16(c, a, b0, b1)                                                    \
    asm volatile(                                                               \
        "mma.sync.aligned.m16n8k16.row.col.f32.f16.f16.f32 "                    \
        "{%0,%1,%2,%3}, {%4,%5,%6,%7}, {%8,%9}, {%0,%1,%2,%3};"                 \
        : "+f"((c)[0]), "+f"((c)[1]), "+f"((c)[2]), "+f"((c)[3])                \
        : "r"((a)[0]), "r"((a)[1]), "r"((a)[2]), "r"((a)[3]), "r"(b0), "r"(b1))

__device__ __forceinline__ uint32_t pack_h2(float a, float b) {
    __half2 t = __floats2half2_rn(a, b);
    return *reinterpret_cast<uint32_t*>(&t);
}
__device__ __forceinline__ float clip1f(float x) { return fminf(fmaxf(x, -1.f), 1.f); }

// ---------------------------------------------------------------------------
// KAN activation (constant-folded partial Cox-de Boor; validated R4..R12).
// ---------------------------------------------------------------------------
__device__ __forceinline__ float kan_eval(float x, const float* __restrict__ cps, float rwv) {
    float t = tanhf(x);
    const float kn[12] = {-1.f, -1.f, -1.f, -1.f, -0.6f, -0.2f, 0.2f, 0.6f, 1.f, 1.f, 1.f, 1.f};
    float c[8];
#pragma unroll
    for (int i = 0; i < 8; ++i) c[i] = (t >= kn[i] && t < kn[i + 1]) ? 1.f : 0.f;
#pragma unroll
    for (int dg = 1; dg <= 3; ++dg) {
#pragma unroll
        for (int i = 0; i < 7; ++i) {
            if (i < 8 - dg) {
                const float d1 = kn[i + dg] - kn[i];
                const float d2 = kn[i + dg + 1] - kn[i + 1];
                float t1 = (d1 > 1e-10f) ? ((t - kn[i]) * (1.0f / d1)) * c[i] : 0.f;
                float t2 = (d2 > 1e-10f) ? ((kn[i + dg + 1] - t) * (1.0f / d2)) * c[i + 1] : 0.f;
                c[i] = t1 + t2;
            }
        }
    }
    float s = 0.f;
#pragma unroll
    for (int j = 0; j < 8; ++j) s = fmaf(c[j], cps[j], s);
    s *= rwv;
    return fminf(fmaxf(s, -10.f), 10.f);
}

// ===========================================================================
// Weight convert: fp32 -> fp16.
// ===========================================================================
__global__ void wsplit(const float4* __restrict__ w, uint2* __restrict__ h, int n4) {
    int i = blockIdx.x * blockDim.x + threadIdx.x;
    if (i >= n4) return;
    float4 v = w[i];
    h[i] = make_uint2(pack_h2(v.x, v.y), pack_h2(v.z, v.w));
}

// ===========================================================================
// LayerNorm: fp32 -> fp16. 1 row/block, D = 2048.
// ===========================================================================
__global__ void ln_kernel(const float* __restrict__ x, __half* __restrict__ y) {
    const int D = 2048;
    const float* xr = x + (size_t)blockIdx.x * D;
    float s = 0.f, q = 0.f;
#pragma unroll
    for (int it = 0; it < 2; ++it) {
        float4 v = *(const float4*)(xr + threadIdx.x * 4 + it * 1024);
        s += (v.x + v.y) + (v.z + v.w);
        q += v.x * v.x + v.y * v.y + v.z * v.z + v.w * v.w;
    }
#pragma unroll
    for (int o = 16; o > 0; o >>= 1) {
        s += __shfl_xor_sync(~0u, s, o);
        q += __shfl_xor_sync(~0u, q, o);
    }
    __shared__ float ss[8], qq[8], mu_s, inv_s;
    if ((threadIdx.x & 31) == 0) { ss[threadIdx.x >> 5] = s; qq[threadIdx.x >> 5] = q; }
    __syncthreads();
    if (threadIdx.x == 0) {
        float ts = 0.f, tq = 0.f;
#pragma unroll
        for (int i = 0; i < 8; ++i) { ts += ss[i]; tq += qq[i]; }
        float mu = ts * (1.f / D);
        mu_s = mu;
        inv_s = rsqrtf(tq * (1.f / D) - mu * mu + 1e-5f);
    }
    __syncthreads();
    const float mu = mu_s, inv = inv_s;
    const size_t rb = (size_t)blockIdx.x * D;
#pragma unroll
    for (int it = 0; it < 2; ++it) {
        int i = threadIdx.x * 4 + it * 1024;
        float4 v = *(const float4*)(xr + i);
        *(uint2*)(y + rb + i) =
            make_uint2(pack_h2((v.x - mu) * inv, (v.y - mu) * inv),
                       pack_h2((v.z - mu) * inv, (v.w - mu) * inv));
    }
}

// ===========================================================================
// GEMM via mma.sync m16n8k16 fp16, single product, fp32 accumulator.
// Templated on MF = warp-tile rows / 16:
//   MF=4: BM=128, grid (N/128, M/128)  — GEMM1/2 (already 256 CTAs)
//   MF=2: BM=64,  grid (N/128, M/64)   — GEMM3/4 (128 -> 256 CTAs, restores
//                                        2-CTA/SM co-residency duty cycle)
// BN=128, BK=32, 8 warps, 3-stage cp.async, 80B-pitch rows, 2 CTAs/SM.
// Per-output-element FP sequence identical across MF -> bit-identical output.
// KAN=1: bias + spline + pair transform -> fp16 out.  KAN=0: fp32 out.
// ===========================================================================
template <int KAN, int MF>
__global__ void __launch_bounds__(256, 2)
gemm_mma(const __half* __restrict__ A, const __half* __restrict__ Wh,
         const float* __restrict__ bias, const float* __restrict__ cp,
         const float* __restrict__ rw, float* __restrict__ Cf,
         __half* __restrict__ Ch, int N, int K) {
    extern __shared__ char smem[];
    float* smf = (float*)smem;
    const uint32_t sb = smem_u32(smem);
    constexpr int A_ROWS = 32 * MF;                 // 128 or 64
    constexpr uint32_t PARAMB = 5120;
    constexpr uint32_t A_BYTES = A_ROWS * 80;       // 10240 or 5120
    constexpr uint32_t STAGE = A_BYTES + 10240;     // 20480 or 15360

    const int tid = threadIdx.x, lane = tid & 31, wid = tid >> 5;
    const int warp_m = wid & 1, warp_n = wid >> 1;
    const int row0 = blockIdx.y * A_ROWS, col0 = blockIdx.x * 128;

    for (int i = tid; i < 128; i += 256) {
        smf[i] = bias[col0 + i];
        if (KAN) smf[128 + i] = rw[col0 + i];
    }
    if (KAN)
        for (int i = tid; i < 1024; i += 256)
            smf[256 + i] = cp[(size_t)(col0 + (i >> 3)) * 9 + (i & 7)];

    // loader: (A_ROWS + 128) rows x 4 x 16B chunks per stage
    auto issue = [&](int kt, int st) {
        constexpr int NCH = (A_ROWS + 128) * 4;     // 1024 or 768
#pragma unroll
        for (int i = 0; i < NCH / 256; ++i) {
            int id = tid + 256 * i;
            const __half* gp;
            uint32_t sa;
            if (id < A_ROWS * 4) {
                int r = id >> 2, c16 = id & 3;
                gp = A + (size_t)(row0 + r) * K + kt * 32 + c16 * 8;
                sa = sb + PARAMB + st * STAGE + r * 80 + c16 * 16;
            } else {
                int id2 = id - A_ROWS * 4;
                int r = id2 >> 2, c16 = id2 & 3;
                gp = Wh + (size_t)(col0 + r) * K + kt * 32 + c16 * 8;
                sa = sb + PARAMB + st * STAGE + A_BYTES + r * 80 + c16 * 16;
            }
            CP_ASYNC16(sa, gp);
        }
    };

    const int NC = K >> 5;
    issue(0, 0); CP_COMMIT();
    issue(1, 1); CP_COMMIT();

    float acc[MF][4][4];
#pragma unroll
    for (int a = 0; a < MF; ++a)
#pragma unroll
        for (int b = 0; b < 4; ++b)
#pragma unroll
            for (int d = 0; d < 4; ++d) acc[a][b][d] = 0.f;

    uint32_t a_row[MF], b_row[2];
#pragma unroll
    for (int mf = 0; mf < MF; ++mf)
        a_row[mf] = (uint32_t)(warp_m * 16 * MF + mf * 16 + (lane & 15)) * 80;
#pragma unroll
    for (int nf2 = 0; nf2 < 2; ++nf2)
        b_row[nf2] =
            (uint32_t)(warp_n * 32 + nf2 * 16 + (lane & 7) + ((lane >> 4) & 1) * 8) * 80;
    const uint32_t a_koff = (uint32_t)(lane >> 4) * 16;
    const uint32_t b_koff = (uint32_t)((lane >> 3) & 1) * 16;

    for (int kt = 0; kt < NC; ++kt) {
        CP_WAIT1();
        __syncthreads();
        const int nx = kt + 2;
        if (nx < NC) issue(nx, nx % 3);
        CP_COMMIT();

        const uint32_t base = sb + PARAMB + (uint32_t)(kt % 3) * STAGE;
#pragma unroll
        for (int k16 = 0; k16 < 2; ++k16) {
            const uint32_t kb = (uint32_t)k16 * 32;
            uint32_t ah[MF][4], bh[4][2];
#pragma unroll
            for (int nf2 = 0; nf2 < 2; ++nf2) {
                uint32_t r0, r1, r2, r3;
                LDMX4(r0, r1, r2, r3, base + A_BYTES + b_row[nf2] + kb + b_koff);
                bh[nf2 * 2][0] = r0; bh[nf2 * 2][1] = r1;
                bh[nf2 * 2 + 1][0] = r2; bh[nf2 * 2 + 1][1] = r3;
            }
#pragma unroll
            for (int mf = 0; mf < MF; ++mf)
                LDMX4(ah[mf][0], ah[mf][1], ah[mf][2], ah[mf][3],
                      base + a_row[mf] + kb + a_koff);
#pragma unroll
            for (int mf = 0; mf < MF; ++mf)
#pragma unroll
                for (int nf = 0; nf < 4; ++nf)
                    MMAF16(acc[mf][nf], ah[mf], bh[nf][0], bh[nf][1]);
        }
    }

    // ---- epilogue: generator g = lane & 3; g in {2,3} -> identity ----
    const int g = lane & 3;
    const float cA = (g < 2) ? 0.05f : 0.f;
    const float sgn = (g == 1) ? -1.f : 1.f;

#pragma unroll
    for (int nf = 0; nf < 4; ++nf) {
        const int cl = warp_n * 32 + nf * 8 + 2 * (lane & 3);
        const float b0 = smf[cl], b1 = smf[cl + 1];
        float rw0 = 0.f, rw1 = 0.f, cps0[8], cps1[8];
        if (KAN) {
            rw0 = smf[128 + cl];
            rw1 = smf[128 + cl + 1];
#pragma unroll
            for (int j = 0; j < 8; ++j) {
                cps0[j] = smf[256 + cl * 8 + j];
                cps1[j] = smf[256 + (cl + 1) * 8 + j];
            }
        }
#pragma unroll
        for (int mf = 0; mf < MF; ++mf) {
            const int m0 = row0 + warp_m * 16 * MF + mf * 16 + (lane >> 2);
            float v0 = acc[mf][nf][0] + b0, v1 = acc[mf][nf][1] + b1;
            float v2 = acc[mf][nf][2] + b0, v3 = acc[mf][nf][3] + b1;
            if (KAN) {
                v0 = kan_eval(v0, cps0, rw0);
                v1 = kan_eval(v1, cps1, rw1);
                v2 = kan_eval(v2, cps0, rw0);
                v3 = kan_eval(v3, cps1, rw1);
                float t = v0;
                v0 = fmaf(cA, clip1f(sgn * v1), v0);
                v1 = fmaf(cA, clip1f(t), v1);
                t = v2;
                v2 = fmaf(cA, clip1f(sgn * v3), v2);
                v3 = fmaf(cA, clip1f(t), v3);
                const size_t i0 = (size_t)m0 * N + col0 + cl;
                const size_t i1 = (size_t)(m0 + 8) * N + col0 + cl;
                *(uint32_t*)(Ch + i0) = pack_h2(v0, v1);
                *(uint32_t*)(Ch + i1) = pack_h2(v2, v3);
            } else {
                const size_t i0 = (size_t)m0 * N + col0 + cl;
                const size_t i1 = (size_t)(m0 + 8) * N + col0 + cl;
                *(float2*)(Cf + i0) = make_float2(v0, v1);
                *(float2*)(Cf + i1) = make_float2(v2, v3);
            }
        }
    }
}

// ===========================================================================
// Launch. R12's guard-passing fork/join (1 side stream, 2 events) retained;
// GEMM3/4 switch to MF=2 (BM=64) for 256-CTA grids.
// ===========================================================================
static constexpr int SMEM_MF4 = 5120 + 3 * 20480;  // 66560
static constexpr int SMEM_MF2 = 5120 + 3 * 15360;  // 51200

extern "C" void kernel_launch(void* const* d_in, const int* in_sizes, int n_in,
                              void* d_out, int out_size) {
    const float* x = (const float*)d_in[0];
    const float* W1 = (const float*)d_in[1];
    const float* b1 = (const float*)d_in[2];
    const float* cp1 = (const float*)d_in[3];
    const float* rw1 = (const float*)d_in[4];
    const float* W2 = (const float*)d_in[5];
    const float* b2 = (const float*)d_in[6];
    const float* cp2 = (const float*)d_in[7];
    const float* rw2 = (const float*)d_in[8];
    const float* W3 = (const float*)d_in[9];
    const float* b3 = (const float*)d_in[10];
    const float* cp3 = (const float*)d_in[11];
    const float* rw3 = (const float*)d_in[12];
    const float* Wo = (const float*)d_in[13];
    const float* bo = (const float*)d_in[14];

    static __half *A = nullptr, *B, *Wh;
    static cudaStream_t s_side = nullptr;
    static cudaEvent_t ev_fork = nullptr, ev_join = nullptr;
    if (!A) {
        cudaGetSymbolAddress((void**)&A, g_A);
        cudaGetSymbolAddress((void**)&B, g_B);
        cudaGetSymbolAddress((void**)&Wh, g_Wh);
        cudaFuncSetAttribute(gemm_mma<1, 4>, cudaFuncAttributeMaxDynamicSharedMemorySize, SMEM_MF4);
        cudaFuncSetAttribute(gemm_mma<1, 2>, cudaFuncAttributeMaxDynamicSharedMemorySize, SMEM_MF2);
        cudaFuncSetAttribute(gemm_mma<0, 2>, cudaFuncAttributeMaxDynamicSharedMemorySize, SMEM_MF2);
        cudaStreamCreateWithFlags(&s_side, cudaStreamNonBlocking);
        cudaEventCreateWithFlags(&ev_fork, cudaEventDisableTiming);
        cudaEventCreateWithFlags(&ev_join, cudaEventDisableTiming);
    }

    // ---- fork: side stream converts W2/W3/Wo while main runs W1+LN+GEMM1 ----
    cudaEventRecord(ev_fork, 0);
    cudaStreamWaitEvent(s_side, ev_fork, 0);
    wsplit<<<16777216 / 4 / 256, 256, 0, s_side>>>((const float4*)W2,
                                                   (uint2*)(Wh + W_OFF2), 16777216 / 4);
    wsplit<<<8388608 / 4 / 256, 256, 0, s_side>>>((const float4*)W3,
                                                  (uint2*)(Wh + W_OFF3), 8388608 / 4);
    wsplit<<<4194304 / 4 / 256, 256, 0, s_side>>>((const float4*)Wo,
                                                  (uint2*)(Wh + W_OFFO), 4194304 / 4);
    cudaEventRecord(ev_join, s_side);

    // ---- main stream: W1 convert + LN + GEMM1 ----
    wsplit<<<8388608 / 4 / 256, 256>>>((const float4*)W1, (uint2*)(Wh + W_OFF1), 8388608 / 4);
    ln_kernel<<<1024, 256>>>(x, A);
    gemm_mma<1, 4><<<dim3(32, 8), 256, SMEM_MF4>>>(A, Wh + W_OFF1, b1, cp1, rw1,
                                                   nullptr, B, 4096, 2048);

    // ---- join before GEMM2 needs W2 ----
    cudaStreamWaitEvent(0, ev_join, 0);

    gemm_mma<1, 4><<<dim3(32, 8), 256, SMEM_MF4>>>(B, Wh + W_OFF2, b2, cp2, rw2,
                                                   nullptr, A, 4096, 4096);
    gemm_mma<1, 2><<<dim3(16, 16), 256, SMEM_MF2>>>(A, Wh + W_OFF3, b3, cp3, rw3,
                                                    nullptr, B, 2048, 4096);
    gemm_mma<0, 2><<<dim3(16, 16), 256, SMEM_MF2>>>(B, Wh + W_OFFO, bo, nullptr,
                                                    nullptr, (float*)d_out, nullptr,
                                                    2048, 2048);
}

// round 17
// speedup vs baseline: 2.7552x; 1.0315x over previous
#include <cuda_runtime.h>
#include <cuda_fp16.h>
#include <cstdint>

// ===========================================================================
// Scratch (static __device__ globals — no runtime allocation).
// ===========================================================================
__device__ __half g_A[1024 * 4096];
__device__ __half g_B[1024 * 4096];
__device__ __half g_Wh[37748736];

static const size_t W_OFF1 = 0;
static const size_t W_OFF2 = 8388608;
static const size_t W_OFF3 = 25165824;
static const size_t W_OFFO = 33554432;

// ===========================================================================
// PTX helpers (sm_80-era, valid on plain compute_103)
// ===========================================================================
__device__ __forceinline__ uint32_t smem_u32(const void* p) {
    uint32_t a;
    asm("{ .reg .u64 t; cvta.to.shared.u64 t, %1; cvt.u32.u64 %0, t; }" : "=r"(a) : "l"(p));
    return a;
}
#define CP_ASYNC16(sa, ga) \
    asm volatile("cp.async.cg.shared.global [%0], [%1], 16;" ::"r"(sa), "l"(ga) : "memory")
#define CP_COMMIT() asm volatile("cp.async.commit_group;" ::: "memory")
#define CP_WAIT1() asm volatile("cp.async.wait_group 1;" ::: "memory")

#define LDMX4(r0, r1, r2, r3, addr)                                              \
    asm volatile("ldmatrix.sync.aligned.m8n8.x4.shared.b16 {%0,%1,%2,%3}, [%4];" \
                 : "=r"(r0), "=r"(r1), "=r"(r2), "=r"(r3) : "r"(addr))

#define MMAF16(c, a, b0, b1)                                                    \
    asm volatile(                                                               \
        "mma.sync.aligned.m16n8k16.row.col.f32.f16.f16.f32 "                    \
        "{%0,%1,%2,%3}, {%4,%5,%6,%7}, {%8,%9}, {%0,%1,%2,%3};"                 \
        : "+f"((c)[0]), "+f"((c)[1]), "+f"((c)[2]), "+f"((c)[3])                \
        : "r"((a)[0]), "r"((a)[1]), "r"((a)[2]), "r"((a)[3]), "r"(b0), "r"(b1))

__device__ __forceinline__ uint32_t pack_h2(float a, float b) {
    __half2 t = __floats2half2_rn(a, b);
    return *reinterpret_cast<uint32_t*>(&t);
}
__device__ __forceinline__ float clip1f(float x) { return fminf(fmaxf(x, -1.f), 1.f); }

// ---------------------------------------------------------------------------
// KAN activation (constant-folded partial Cox-de Boor; validated R4..R16).
// ---------------------------------------------------------------------------
__device__ __forceinline__ float kan_eval(float x, const float* __restrict__ cps, float rwv) {
    float t = tanhf(x);
    const float kn[12] = {-1.f, -1.f, -1.f, -1.f, -0.6f, -0.2f, 0.2f, 0.6f, 1.f, 1.f, 1.f, 1.f};
    float c[8];
#pragma unroll
    for (int i = 0; i < 8; ++i) c[i] = (t >= kn[i] && t < kn[i + 1]) ? 1.f : 0.f;
#pragma unroll
    for (int dg = 1; dg <= 3; ++dg) {
#pragma unroll
        for (int i = 0; i < 7; ++i) {
            if (i < 8 - dg) {
                const float d1 = kn[i + dg] - kn[i];
                const float d2 = kn[i + dg + 1] - kn[i + 1];
                float t1 = (d1 > 1e-10f) ? ((t - kn[i]) * (1.0f / d1)) * c[i] : 0.f;
                float t2 = (d2 > 1e-10f) ? ((kn[i + dg + 1] - t) * (1.0f / d2)) * c[i + 1] : 0.f;
                c[i] = t1 + t2;
            }
        }
    }
    float s = 0.f;
#pragma unroll
    for (int j = 0; j < 8; ++j) s = fmaf(c[j], cps[j], s);
    s *= rwv;
    return fminf(fmaxf(s, -10.f), 10.f);
}

// ===========================================================================
// Weight convert: fp32 -> fp16.
// ===========================================================================
__global__ void wsplit(const float4* __restrict__ w, uint2* __restrict__ h, int n4) {
    int i = blockIdx.x * blockDim.x + threadIdx.x;
    if (i >= n4) return;
    float4 v = w[i];
    h[i] = make_uint2(pack_h2(v.x, v.y), pack_h2(v.z, v.w));
}

// ===========================================================================
// LayerNorm: fp32 -> fp16. 1 row/block, D = 2048.
// ===========================================================================
__global__ void ln_kernel(const float* __restrict__ x, __half* __restrict__ y) {
    const int D = 2048;
    const float* xr = x + (size_t)blockIdx.x * D;
    float s = 0.f, q = 0.f;
#pragma unroll
    for (int it = 0; it < 2; ++it) {
        float4 v = *(const float4*)(xr + threadIdx.x * 4 + it * 1024);
        s += (v.x + v.y) + (v.z + v.w);
        q += v.x * v.x + v.y * v.y + v.z * v.z + v.w * v.w;
    }
#pragma unroll
    for (int o = 16; o > 0; o >>= 1) {
        s += __shfl_xor_sync(~0u, s, o);
        q += __shfl_xor_sync(~0u, q, o);
    }
    __shared__ float ss[8], qq[8], mu_s, inv_s;
    if ((threadIdx.x & 31) == 0) { ss[threadIdx.x >> 5] = s; qq[threadIdx.x >> 5] = q; }
    __syncthreads();
    if (threadIdx.x == 0) {
        float ts = 0.f, tq = 0.f;
#pragma unroll
        for (int i = 0; i < 8; ++i) { ts += ss[i]; tq += qq[i]; }
        float mu = ts * (1.f / D);
        mu_s = mu;
        inv_s = rsqrtf(tq * (1.f / D) - mu * mu + 1e-5f);
    }
    __syncthreads();
    const float mu = mu_s, inv = inv_s;
    const size_t rb = (size_t)blockIdx.x * D;
#pragma unroll
    for (int it = 0; it < 2; ++it) {
        int i = threadIdx.x * 4 + it * 1024;
        float4 v = *(const float4*)(xr + i);
        *(uint2*)(y + rb + i) =
            make_uint2(pack_h2((v.x - mu) * inv, (v.y - mu) * inv),
                       pack_h2((v.z - mu) * inv, (v.w - mu) * inv));
    }
}

// ===========================================================================
// GEMM via mma.sync m16n8k16 fp16, single product, fp32 accumulator.
// BK=64, 2-stage cp.async pipeline (bytes-in-flight equal to R16's 3xBK32),
// 144B-pitch rows (16B-bank stride 9 == 1 mod 8 -> ldmatrix conflict-free).
// Templated on MF: MF=4 -> BM=128 (GEMM1/2), MF=2 -> BM=64 (GEMM3/4).
// BN=128, 8 warps, 2 CTAs/SM. k-accumulation order identical to R16 ->
// bit-identical output.
// KAN=1: bias + spline + pair transform -> fp16 out.  KAN=0: fp32 out.
// ===========================================================================
template <int KAN, int MF>
__global__ void __launch_bounds__(256, 2)
gemm_mma(const __half* __restrict__ A, const __half* __restrict__ Wh,
         const float* __restrict__ bias, const float* __restrict__ cp,
         const float* __restrict__ rw, float* __restrict__ Cf,
         __half* __restrict__ Ch, int N, int K) {
    extern __shared__ char smem[];
    float* smf = (float*)smem;
    const uint32_t sb = smem_u32(smem);
    constexpr int A_ROWS = 32 * MF;                  // 128 or 64
    constexpr uint32_t PARAMB = 5120;
    constexpr uint32_t P = 144;                      // row pitch (128 data + 16 pad)
    constexpr uint32_t A_BYTES = A_ROWS * P;         // 18432 or 9216
    constexpr uint32_t STAGE = A_BYTES + 128 * P;    // 36864 or 27648

    const int tid = threadIdx.x, lane = tid & 31, wid = tid >> 5;
    const int warp_m = wid & 1, warp_n = wid >> 1;
    const int row0 = blockIdx.y * A_ROWS, col0 = blockIdx.x * 128;

    for (int i = tid; i < 128; i += 256) {
        smf[i] = bias[col0 + i];
        if (KAN) smf[128 + i] = rw[col0 + i];
    }
    if (KAN)
        for (int i = tid; i < 1024; i += 256)
            smf[256 + i] = cp[(size_t)(col0 + (i >> 3)) * 9 + (i & 7)];

    // loader: (A_ROWS + 128) rows x 8 x 16B chunks per stage
    auto issue = [&](int kt, int st) {
        constexpr int NCH = (A_ROWS + 128) * 8;      // 2048 or 1536
#pragma unroll
        for (int i = 0; i < NCH / 256; ++i) {
            int id = tid + 256 * i;
            const __half* gp;
            uint32_t sa;
            if (id < A_ROWS * 8) {
                int r = id >> 3, c16 = id & 7;
                gp = A + (size_t)(row0 + r) * K + kt * 64 + c16 * 8;
                sa = sb + PARAMB + st * STAGE + r * P + c16 * 16;
            } else {
                int id2 = id - A_ROWS * 8;
                int r = id2 >> 3, c16 = id2 & 7;
                gp = Wh + (size_t)(col0 + r) * K + kt * 64 + c16 * 8;
                sa = sb + PARAMB + st * STAGE + A_BYTES + r * P + c16 * 16;
            }
            CP_ASYNC16(sa, gp);
        }
    };

    const int NC = K >> 6;  // chunks of 64
    issue(0, 0); CP_COMMIT();
    issue(1, 1); CP_COMMIT();

    float acc[MF][4][4];
#pragma unroll
    for (int a = 0; a < MF; ++a)
#pragma unroll
        for (int b = 0; b < 4; ++b)
#pragma unroll
            for (int d = 0; d < 4; ++d) acc[a][b][d] = 0.f;

    uint32_t a_row[MF], b_row[2];
#pragma unroll
    for (int mf = 0; mf < MF; ++mf)
        a_row[mf] = (uint32_t)(warp_m * 16 * MF + mf * 16 + (lane & 15)) * P;
#pragma unroll
    for (int nf2 = 0; nf2 < 2; ++nf2)
        b_row[nf2] =
            (uint32_t)(warp_n * 32 + nf2 * 16 + (lane & 7) + ((lane >> 4) & 1) * 8) * P;
    const uint32_t a_koff = (uint32_t)(lane >> 4) * 16;
    const uint32_t b_koff = (uint32_t)((lane >> 3) & 1) * 16;

    for (int kt = 0; kt < NC; ++kt) {
        CP_WAIT1();
        __syncthreads();

        const uint32_t base = sb + PARAMB + (uint32_t)(kt & 1) * STAGE;
#pragma unroll
        for (int k16 = 0; k16 < 4; ++k16) {
            const uint32_t kb = (uint32_t)k16 * 32;  // 16 halves = 32 B
            uint32_t ah[MF][4], bh[4][2];
#pragma unroll
            for (int nf2 = 0; nf2 < 2; ++nf2) {
                uint32_t r0, r1, r2, r3;
                LDMX4(r0, r1, r2, r3, base + A_BYTES + b_row[nf2] + kb + b_koff);
                bh[nf2 * 2][0] = r0; bh[nf2 * 2][1] = r1;
                bh[nf2 * 2 + 1][0] = r2; bh[nf2 * 2 + 1][1] = r3;
            }
#pragma unroll
            for (int mf = 0; mf < MF; ++mf)
                LDMX4(ah[mf][0], ah[mf][1], ah[mf][2], ah[mf][3],
                      base + a_row[mf] + kb + a_koff);
#pragma unroll
            for (int mf = 0; mf < MF; ++mf)
#pragma unroll
                for (int nf = 0; nf < 4; ++nf)
                    MMAF16(acc[mf][nf], ah[mf], bh[nf][0], bh[nf][1]);
        }

        __syncthreads();  // all warps done reading this stage before refill
        const int nx = kt + 2;
        if (nx < NC) issue(nx, kt & 1);
        CP_COMMIT();
    }

    // ---- epilogue: generator g = lane & 3; g in {2,3} -> identity ----
    const int g = lane & 3;
    const float cA = (g < 2) ? 0.05f : 0.f;
    const float sgn = (g == 1) ? -1.f : 1.f;

#pragma unroll
    for (int nf = 0; nf < 4; ++nf) {
        const int cl = warp_n * 32 + nf * 8 + 2 * (lane & 3);
        const float b0 = smf[cl], b1 = smf[cl + 1];
        float rw0 = 0.f, rw1 = 0.f, cps0[8], cps1[8];
        if (KAN) {
            rw0 = smf[128 + cl];
            rw1 = smf[128 + cl + 1];
#pragma unroll
            for (int j = 0; j < 8; ++j) {
                cps0[j] = smf[256 + cl * 8 + j];
                cps1[j] = smf[256 + (cl + 1) * 8 + j];
            }
        }
#pragma unroll
        for (int mf = 0; mf < MF; ++mf) {
            const int m0 = row0 + warp_m * 16 * MF + mf * 16 + (lane >> 2);
            float v0 = acc[mf][nf][0] + b0, v1 = acc[mf][nf][1] + b1;
            float v2 = acc[mf][nf][2] + b0, v3 = acc[mf][nf][3] + b1;
            if (KAN) {
                v0 = kan_eval(v0, cps0, rw0);
                v1 = kan_eval(v1, cps1, rw1);
                v2 = kan_eval(v2, cps0, rw0);
                v3 = kan_eval(v3, cps1, rw1);
                float t = v0;
                v0 = fmaf(cA, clip1f(sgn * v1), v0);
                v1 = fmaf(cA, clip1f(t), v1);
                t = v2;
                v2 = fmaf(cA, clip1f(sgn * v3), v2);
                v3 = fmaf(cA, clip1f(t), v3);
                const size_t i0 = (size_t)m0 * N + col0 + cl;
                const size_t i1 = (size_t)(m0 + 8) * N + col0 + cl;
                *(uint32_t*)(Ch + i0) = pack_h2(v0, v1);
                *(uint32_t*)(Ch + i1) = pack_h2(v2, v3);
            } else {
                const size_t i0 = (size_t)m0 * N + col0 + cl;
                const size_t i1 = (size_t)(m0 + 8) * N + col0 + cl;
                *(float2*)(Cf + i0) = make_float2(v0, v1);
                *(float2*)(Cf + i1) = make_float2(v2, v3);
            }
        }
    }
}

// ===========================================================================
// Launch. Side stream: W1 first (ev_w1) then W2/W3/Wo (ev_join); main: LN
// runs concurrently with W1, GEMM1 waits only on ev_w1.
// ===========================================================================
static constexpr int SMEM_MF4 = 5120 + 2 * 36864;  // 78848 (x2 = 157696)
static constexpr int SMEM_MF2 = 5120 + 2 * 27648;  // 60416 (x2 = 120832)

extern "C" void kernel_launch(void* const* d_in, const int* in_sizes, int n_in,
                              void* d_out, int out_size) {
    const float* x = (const float*)d_in[0];
    const float* W1 = (const float*)d_in[1];
    const float* b1 = (const float*)d_in[2];
    const float* cp1 = (const float*)d_in[3];
    const float* rw1 = (const float*)d_in[4];
    const float* W2 = (const float*)d_in[5];
    const float* b2 = (const float*)d_in[6];
    const float* cp2 = (const float*)d_in[7];
    const float* rw2 = (const float*)d_in[8];
    const float* W3 = (const float*)d_in[9];
    const float* b3 = (const float*)d_in[10];
    const float* cp3 = (const float*)d_in[11];
    const float* rw3 = (const float*)d_in[12];
    const float* Wo = (const float*)d_in[13];
    const float* bo = (const float*)d_in[14];

    static __half *A = nullptr, *B, *Wh;
    static cudaStream_t s_side = nullptr;
    static cudaEvent_t ev_fork = nullptr, ev_w1 = nullptr, ev_join = nullptr;
    if (!A) {
        cudaGetSymbolAddress((void**)&A, g_A);
        cudaGetSymbolAddress((void**)&B, g_B);
        cudaGetSymbolAddress((void**)&Wh, g_Wh);
        cudaFuncSetAttribute(gemm_mma<1, 4>, cudaFuncAttributeMaxDynamicSharedMemorySize, SMEM_MF4);
        cudaFuncSetAttribute(gemm_mma<1, 2>, cudaFuncAttributeMaxDynamicSharedMemorySize, SMEM_MF2);
        cudaFuncSetAttribute(gemm_mma<0, 2>, cudaFuncAttributeMaxDynamicSharedMemorySize, SMEM_MF2);
        cudaStreamCreateWithFlags(&s_side, cudaStreamNonBlocking);
        cudaEventCreateWithFlags(&ev_fork, cudaEventDisableTiming);
        cudaEventCreateWithFlags(&ev_w1, cudaEventDisableTiming);
        cudaEventCreateWithFlags(&ev_join, cudaEventDisableTiming);
    }

    // ---- fork: side stream converts W1 (signal), then W2/W3/Wo (signal) ----
    cudaEventRecord(ev_fork, 0);
    cudaStreamWaitEvent(s_side, ev_fork, 0);
    wsplit<<<8388608 / 4 / 256, 256, 0, s_side>>>((const float4*)W1,
                                                  (uint2*)(Wh + W_OFF1), 8388608 / 4);
    cudaEventRecord(ev_w1, s_side);
    wsplit<<<16777216 / 4 / 256, 256, 0, s_side>>>((const float4*)W2,
                                                   (uint2*)(Wh + W_OFF2), 16777216 / 4);
    wsplit<<<8388608 / 4 / 256, 256, 0, s_side>>>((const float4*)W3,
                                                  (uint2*)(Wh + W_OFF3), 8388608 / 4);
    wsplit<<<4194304 / 4 / 256, 256, 0, s_side>>>((const float4*)Wo,
                                                  (uint2*)(Wh + W_OFFO), 4194304 / 4);
    cudaEventRecord(ev_join, s_side);

    // ---- main stream: LN concurrent with W1 ----
    ln_kernel<<<1024, 256>>>(x, A);
    cudaStreamWaitEvent(0, ev_w1, 0);
    gemm_mma<1, 4><<<dim3(32, 8), 256, SMEM_MF4>>>(A, Wh + W_OFF1, b1, cp1, rw1,
                                                   nullptr, B, 4096, 2048);

    // ---- join before GEMM2 needs W2 ----
    cudaStreamWaitEvent(0, ev_join, 0);

    gemm_mma<1, 4><<<dim3(32, 8), 256, SMEM_MF4>>>(B, Wh + W_OFF2, b2, cp2, rw2,
                                                   nullptr, A, 4096, 4096);
    gemm_mma<1, 2><<<dim3(16, 16), 256, SMEM_MF2>>>(A, Wh + W_OFF3, b3, cp3, rw3,
                                                    nullptr, B, 2048, 4096);
    gemm_mma<0, 2><<<dim3(16, 16), 256, SMEM_MF2>>>(B, Wh + W_OFFO, bo, nullptr,
                                                    nullptr, (float*)d_out, nullptr,
                                                    2048, 2048);
}